// round 1
// baseline (speedup 1.0000x reference)
#include <cuda_runtime.h>
#include <cuda_bf16.h>
#include <math.h>

// Problem constants
#define S_TOK 3072
#define HID 1152
#define NH 16
#define HD 72
#define MLP_DIM 4304
#define QKV_N (3*HID)   // 3456
#define EPS 1e-5f

// ---------------- scratch (allocation-free: __device__ globals) ----------------
__device__ float g_h0[S_TOK*HID];
__device__ float g_qkv[S_TOK*QKV_N];
__device__ float g_attn[S_TOK*HID];
__device__ float g_x2[S_TOK*HID];
__device__ float g_h1[S_TOK*HID];
__device__ float g_mlp[S_TOK*MLP_DIM];

// ---------------- LayerNorm: one block per row ----------------
__global__ void ln_kernel(const float* __restrict__ x, const float* __restrict__ g,
                          const float* __restrict__ b, float* __restrict__ y) {
    __shared__ float row[HID];
    __shared__ float red_s[256], red_ss[256];
    int r = blockIdx.x;
    int tid = threadIdx.x;
    float s = 0.f, ss = 0.f;
    for (int i = tid; i < HID; i += 256) {
        float v = x[(size_t)r*HID + i];
        row[i] = v;
        s += v; ss += v*v;
    }
    red_s[tid] = s; red_ss[tid] = ss;
    __syncthreads();
    for (int o = 128; o > 0; o >>= 1) {
        if (tid < o) { red_s[tid] += red_s[tid+o]; red_ss[tid] += red_ss[tid+o]; }
        __syncthreads();
    }
    float mu = red_s[0] * (1.0f/HID);
    float var = red_ss[0] * (1.0f/HID) - mu*mu;
    float rstd = rsqrtf(var + EPS);
    for (int i = tid; i < HID; i += 256) {
        y[(size_t)r*HID + i] = (row[i] - mu) * rstd * g[i] + b[i];
    }
}

// ---------------- generic tiled SGEMM ----------------
// C[M,N] = A[M,K] @ B[K,N] + bias[N]  (+ residual / gelu depending on mode)
// mode 0: bias; mode 1: bias + residual; mode 2: bias + gelu(tanh)
#define BM 128
#define BN 64
#define BK 16

__device__ __forceinline__ float gelu_tanh(float v) {
    float c = 0.7978845608028654f * (v + 0.044715f * v * v * v);
    return 0.5f * v * (1.0f + tanhf(c));
}

__global__ void __launch_bounds__(256)
sgemm_kernel(const float* __restrict__ A, const float* __restrict__ B,
             const float* __restrict__ bias, const float* __restrict__ residual,
             float* __restrict__ C, int M, int N, int K, int mode) {
    __shared__ float As[BK][BM+4];
    __shared__ float Bs[BK][BN];
    int tid = threadIdx.x;
    int tx = tid & 15, ty = tid >> 4;
    int m0 = blockIdx.y * BM, n0 = blockIdx.x * BN;

    float acc[8][4];
#pragma unroll
    for (int i = 0; i < 8; i++)
#pragma unroll
        for (int j = 0; j < 4; j++) acc[i][j] = 0.f;

    for (int k0 = 0; k0 < K; k0 += BK) {
        // A tile: 128x16 (M,K divisible by tile in all our calls)
#pragma unroll
        for (int i = 0; i < 8; i++) {
            int l = tid + i*256;
            int m = l >> 4, k = l & 15;
            As[k][m] = A[(size_t)(m0+m)*K + k0 + k];
        }
        // B tile: 16x64, N guarded
#pragma unroll
        for (int i = 0; i < 4; i++) {
            int l = tid + i*256;
            int k = l >> 6, n = l & 63;
            int gn = n0 + n;
            Bs[k][n] = (gn < N) ? B[(size_t)(k0+k)*N + gn] : 0.f;
        }
        __syncthreads();
#pragma unroll
        for (int kk = 0; kk < BK; kk++) {
            float4 a0 = *(const float4*)&As[kk][ty*8];
            float4 a1 = *(const float4*)&As[kk][ty*8+4];
            float4 b0 = *(const float4*)&Bs[kk][tx*4];
            float a[8] = {a0.x,a0.y,a0.z,a0.w,a1.x,a1.y,a1.z,a1.w};
            float b[4] = {b0.x,b0.y,b0.z,b0.w};
#pragma unroll
            for (int i = 0; i < 8; i++)
#pragma unroll
                for (int j = 0; j < 4; j++) acc[i][j] = fmaf(a[i], b[j], acc[i][j]);
        }
        __syncthreads();
    }
#pragma unroll
    for (int i = 0; i < 8; i++) {
        int m = m0 + ty*8 + i;
#pragma unroll
        for (int j = 0; j < 4; j++) {
            int n = n0 + tx*4 + j;
            if (n < N) {
                float v = acc[i][j] + bias[n];
                if (mode == 1) v += residual[(size_t)m*N + n];
                else if (mode == 2) v = gelu_tanh(v);
                C[(size_t)m*N + n] = v;
            }
        }
    }
}

// ---------------- RoPE: in-place on q and k sections of qkv ----------------
// qkv row: [3][NH][HD]; fc: (S, HD/2, 2) cos/sin
__global__ void rope_kernel(float* __restrict__ qkv, const float* __restrict__ fc) {
    int idx = blockIdx.x * blockDim.x + threadIdx.x;
    const int PER = S_TOK * NH * (HD/2);   // per q or k
    if (idx >= 2*PER) return;
    int which = idx / PER;        // 0 = q, 1 = k
    int r = idx - which*PER;
    int s = r / (NH*(HD/2));
    int rem = r - s*(NH*(HD/2));
    int h = rem / (HD/2);
    int i = rem - h*(HD/2);
    size_t base = (size_t)s*QKV_N + which*HID + h*HD + 2*i;
    float c  = fc[((size_t)s*(HD/2) + i)*2 + 0];
    float sn = fc[((size_t)s*(HD/2) + i)*2 + 1];
    float a = qkv[base], b = qkv[base+1];
    qkv[base]   = a*c - b*sn;
    qkv[base+1] = a*sn + b*c;
}

// ---------------- Fused flash-style attention ----------------
// grid = (S/64 q-tiles, NH heads), 256 threads
#define AQ 64
#define AK 64
#define QKS 68   // row stride for Qs/Ks/Ps ([d][r] / [r][c])
#define VS 80    // row stride for Vs (72 padded to 80, zero-filled)

__device__ __forceinline__ int seg_of(int t, const int* offs) {
    int s = 0;
#pragma unroll
    for (int i = 1; i <= 6; i++) if (offs[i] <= t) s = i;
    return s;
}

__global__ void __launch_bounds__(256)
attn_kernel(const float* __restrict__ qkv, const int* __restrict__ offs,
            float* __restrict__ out) {
    extern __shared__ float sm[];
    float* Qs = sm;                    // 72 * 68
    float* Ks = Qs + HD*QKS;           // 72 * 68
    float* Vs = Ks + HD*QKS;           // 64 * 80
    float* Ps = Vs + AK*VS;            // 64 * 68
    int*  segq = (int*)(Ps + AQ*QKS);  // 64
    int*  segk = segq + AQ;            // 64

    int h = blockIdx.y;
    int q0 = blockIdx.x * AQ;
    int tid = threadIdx.x;
    int tx = tid & 15, ty = tid >> 4;

    // load Q tile [d][r]
    for (int l = tid; l < AQ*HD; l += 256) {
        int r = l / HD, d = l - r*HD;
        Qs[d*QKS + r] = qkv[(size_t)(q0+r)*QKV_N + h*HD + d];
    }
    if (tid < AQ) segq[tid] = seg_of(q0 + tid, offs);

    float m_i[4], l_i[4], O[4][5];
#pragma unroll
    for (int i = 0; i < 4; i++) {
        m_i[i] = -1e30f; l_i[i] = 0.f;
#pragma unroll
        for (int jj = 0; jj < 5; jj++) O[i][jj] = 0.f;
    }
    const float scale = 0.11785113019775793f;  // 1/sqrt(72)

    for (int j0 = 0; j0 < S_TOK; j0 += AK) {
        __syncthreads();  // previous PV done; Q tile visible (first iter)
        // load K [d][c] and V [c][d] tiles
        for (int l = tid; l < AK*HD; l += 256) {
            int c = l / HD, d = l - c*HD;
            Ks[d*QKS + c] = qkv[(size_t)(j0+c)*QKV_N + HID + h*HD + d];
        }
        for (int l = tid; l < AK*VS; l += 256) {
            int c = l / VS, d = l - c*VS;
            Vs[l] = (d < HD) ? qkv[(size_t)(j0+c)*QKV_N + 2*HID + h*HD + d] : 0.f;
        }
        if (tid < AK) segk[tid] = seg_of(j0 + tid, offs);
        __syncthreads();

        // score tile 4x4 per thread
        float s[4][4];
#pragma unroll
        for (int i = 0; i < 4; i++)
#pragma unroll
            for (int j = 0; j < 4; j++) s[i][j] = 0.f;
#pragma unroll 4
        for (int d = 0; d < HD; d++) {
            float4 qa = *(const float4*)&Qs[d*QKS + ty*4];
            float4 kb = *(const float4*)&Ks[d*QKS + tx*4];
            float a[4] = {qa.x,qa.y,qa.z,qa.w};
            float b[4] = {kb.x,kb.y,kb.z,kb.w};
#pragma unroll
            for (int i = 0; i < 4; i++)
#pragma unroll
                for (int j = 0; j < 4; j++) s[i][j] = fmaf(a[i], b[j], s[i][j]);
        }
        // scale + segment bias (+1.0 same segment — NOT -inf)
#pragma unroll
        for (int i = 0; i < 4; i++) {
            int sq = segq[ty*4+i];
#pragma unroll
            for (int j = 0; j < 4; j++)
                s[i][j] = s[i][j]*scale + ((sq == segk[tx*4+j]) ? 1.0f : 0.0f);
        }
        // online softmax per row (row split across 16 tx lanes)
#pragma unroll
        for (int i = 0; i < 4; i++) {
            float rmax = fmaxf(fmaxf(s[i][0], s[i][1]), fmaxf(s[i][2], s[i][3]));
#pragma unroll
            for (int o = 8; o > 0; o >>= 1)
                rmax = fmaxf(rmax, __shfl_xor_sync(0xffffffffu, rmax, o, 16));
            float mnew = fmaxf(m_i[i], rmax);
            float fac = __expf(m_i[i] - mnew);
            float psum = 0.f;
#pragma unroll
            for (int j = 0; j < 4; j++) {
                float p = __expf(s[i][j] - mnew);
                s[i][j] = p; psum += p;
            }
#pragma unroll
            for (int o = 8; o > 0; o >>= 1)
                psum += __shfl_xor_sync(0xffffffffu, psum, o, 16);
            l_i[i] = l_i[i]*fac + psum;
            m_i[i] = mnew;
#pragma unroll
            for (int jj = 0; jj < 5; jj++) O[i][jj] *= fac;
        }
        // stage P tile
#pragma unroll
        for (int i = 0; i < 4; i++)
#pragma unroll
            for (int j = 0; j < 4; j++)
                Ps[(ty*4+i)*QKS + tx*4 + j] = s[i][j];
        __syncthreads();
        // O += P @ V  (cols owned: d = tx + 16*jj, Vs zero-padded so no guard)
        for (int kk4 = 0; kk4 < AK; kk4 += 4) {
            float4 p4[4];
#pragma unroll
            for (int i = 0; i < 4; i++)
                p4[i] = *(const float4*)&Ps[(ty*4+i)*QKS + kk4];
#pragma unroll
            for (int u = 0; u < 4; u++) {
                int kk = kk4 + u;
                float v[5];
#pragma unroll
                for (int jj = 0; jj < 5; jj++) v[jj] = Vs[kk*VS + tx + 16*jj];
                float pv[4] = {
                    (u==0)?p4[0].x:(u==1)?p4[0].y:(u==2)?p4[0].z:p4[0].w,
                    (u==0)?p4[1].x:(u==1)?p4[1].y:(u==2)?p4[1].z:p4[1].w,
                    (u==0)?p4[2].x:(u==1)?p4[2].y:(u==2)?p4[2].z:p4[2].w,
                    (u==0)?p4[3].x:(u==1)?p4[3].y:(u==2)?p4[3].z:p4[3].w };
#pragma unroll
                for (int i = 0; i < 4; i++)
#pragma unroll
                    for (int jj = 0; jj < 5; jj++)
                        O[i][jj] = fmaf(pv[i], v[jj], O[i][jj]);
            }
        }
    }
    // epilogue
#pragma unroll
    for (int i = 0; i < 4; i++) {
        float inv = 1.0f / l_i[i];
        int r = q0 + ty*4 + i;
#pragma unroll
        for (int jj = 0; jj < 5; jj++) {
            int d = tx + 16*jj;
            if (d < HD)
                out[(size_t)r*HID + h*HD + d] = O[i][jj] * inv;
        }
    }
}

// ---------------- launch ----------------
extern "C" void kernel_launch(void* const* d_in, const int* in_sizes, int n_in,
                              void* d_out, int out_size) {
    const float* x      = (const float*)d_in[0];
    const int*   offs   = (const int*)  d_in[1];
    const float* fc     = (const float*)d_in[2];
    const float* ln0_g  = (const float*)d_in[3];
    const float* ln0_b  = (const float*)d_in[4];
    const float* wqkv_w = (const float*)d_in[5];
    const float* wqkv_b = (const float*)d_in[6];
    const float* wo_w   = (const float*)d_in[7];
    const float* wo_b   = (const float*)d_in[8];
    const float* ln1_g  = (const float*)d_in[9];
    const float* ln1_b  = (const float*)d_in[10];
    const float* w1     = (const float*)d_in[11];
    const float* b1     = (const float*)d_in[12];
    const float* w2     = (const float*)d_in[13];
    const float* b2     = (const float*)d_in[14];
    float* out = (float*)d_out;

    float *h0, *qkv, *attn, *x2, *h1, *mlp;
    cudaGetSymbolAddress((void**)&h0,   g_h0);
    cudaGetSymbolAddress((void**)&qkv,  g_qkv);
    cudaGetSymbolAddress((void**)&attn, g_attn);
    cudaGetSymbolAddress((void**)&x2,   g_x2);
    cudaGetSymbolAddress((void**)&h1,   g_h1);
    cudaGetSymbolAddress((void**)&mlp,  g_mlp);

    // attention dynamic smem
    const int ATTN_SMEM = (HD*QKS + HD*QKS + AK*VS + AQ*QKS) * 4 + 2*AQ*4;
    cudaFuncSetAttribute(attn_kernel, cudaFuncAttributeMaxDynamicSharedMemorySize, ATTN_SMEM);

    // 1. LN0
    ln_kernel<<<S_TOK, 256>>>(x, ln0_g, ln0_b, h0);
    // 2. QKV = h0 @ wqkv + b
    sgemm_kernel<<<dim3(QKV_N/BN, S_TOK/BM), 256>>>(h0, wqkv_w, wqkv_b, nullptr, qkv,
                                                    S_TOK, QKV_N, HID, 0);
    // 3. RoPE on q,k
    {
        int total = 2 * S_TOK * NH * (HD/2);
        rope_kernel<<<(total + 255)/256, 256>>>(qkv, fc);
    }
    // 4. attention
    attn_kernel<<<dim3(S_TOK/AQ, NH), 256, ATTN_SMEM>>>(qkv, offs, attn);
    // 5. x2 = x + attn @ wo + b
    sgemm_kernel<<<dim3(HID/BN, S_TOK/BM), 256>>>(attn, wo_w, wo_b, x, x2,
                                                  S_TOK, HID, HID, 1);
    // 6. LN1
    ln_kernel<<<S_TOK, 256>>>(x2, ln1_g, ln1_b, h1);
    // 7. mlp = gelu(h1 @ w1 + b1)
    sgemm_kernel<<<dim3((MLP_DIM+BN-1)/BN, S_TOK/BM), 256>>>(h1, w1, b1, nullptr, mlp,
                                                             S_TOK, MLP_DIM, HID, 2);
    // 8. out = x2 + mlp @ w2 + b2
    sgemm_kernel<<<dim3(HID/BN, S_TOK/BM), 256>>>(mlp, w2, b2, x2, out,
                                                  S_TOK, HID, MLP_DIM, 1);
}

// round 2
// speedup vs baseline: 1.5230x; 1.5230x over previous
#include <cuda_runtime.h>
#include <cuda_bf16.h>
#include <math.h>

// Problem constants
#define S_TOK 3072
#define HID 1152
#define NH 16
#define HD 72
#define MLP_DIM 4304
#define QKV_N (3*HID)   // 3456
#define EPS 1e-5f

// ---------------- scratch (allocation-free: __device__ globals) ----------------
__device__ float g_h0[S_TOK*HID];
__device__ float g_qkv[S_TOK*QKV_N];
__device__ float g_attn[S_TOK*HID];
__device__ float g_x2[S_TOK*HID];
__device__ float g_h1[S_TOK*HID];
__device__ float g_mlp[S_TOK*MLP_DIM];

// ---------------- LayerNorm: one block per row ----------------
__global__ void ln_kernel(const float* __restrict__ x, const float* __restrict__ g,
                          const float* __restrict__ b, float* __restrict__ y) {
    __shared__ float row[HID];
    __shared__ float red_s[256], red_ss[256];
    int r = blockIdx.x;
    int tid = threadIdx.x;
    float s = 0.f, ss = 0.f;
    for (int i = tid; i < HID; i += 256) {
        float v = x[(size_t)r*HID + i];
        row[i] = v;
        s += v; ss += v*v;
    }
    red_s[tid] = s; red_ss[tid] = ss;
    __syncthreads();
    for (int o = 128; o > 0; o >>= 1) {
        if (tid < o) { red_s[tid] += red_s[tid+o]; red_ss[tid] += red_ss[tid+o]; }
        __syncthreads();
    }
    float mu = red_s[0] * (1.0f/HID);
    float var = red_ss[0] * (1.0f/HID) - mu*mu;
    float rstd = rsqrtf(var + EPS);
    for (int i = tid; i < HID; i += 256) {
        y[(size_t)r*HID + i] = (row[i] - mu) * rstd * g[i] + b[i];
    }
}

// ---------------- tf32 tensor-core GEMM ----------------
// C[M,N] = A[M,K] @ B[K,N] + bias[N] (+ residual / gelu by mode)
// Block tile 128x64, BK=16. 8 warps in 4(M) x 2(N) grid, 32x32 per warp.
// Each warp: 2 m16 tiles x 4 n8 tiles of mma.m16n8k8.tf32.
#define BM 128
#define BN 64
#define BK 16
#define AST 20   // As row stride (floats): banks (20*r+c)%32 distinct for frag pattern
#define BST 72   // Bs row stride: banks (72*k+n)%32 = (8k+n)%32 distinct

__device__ __forceinline__ float gelu_tanh(float v) {
    float c = 0.7978845608028654f * (v + 0.044715f * v * v * v);
    return 0.5f * v * (1.0f + tanhf(c));
}

__device__ __forceinline__ float to_tf32(float x) {
    unsigned r;
    asm("cvt.rna.tf32.f32 %0, %1;" : "=r"(r) : "f"(x));
    return __uint_as_float(r);
}

__global__ void __launch_bounds__(256)
mma_gemm_kernel(const float* __restrict__ A, const float* __restrict__ B,
                const float* __restrict__ bias, const float* __restrict__ residual,
                float* __restrict__ C, int M, int N, int K, int mode) {
    __shared__ float As[BM][AST];   // [m][k], tf32-rounded
    __shared__ float Bs[BK][BST];   // [k][n], tf32-rounded

    int tid  = threadIdx.x;
    int warp = tid >> 5;
    int lane = tid & 31;
    int wy = warp >> 1;          // 0..3  (M direction, 32 rows each)
    int wx = warp & 1;           // 0..1  (N direction, 32 cols each)
    int m0 = blockIdx.y * BM;
    int n0 = blockIdx.x * BN;

    int g  = lane >> 2;          // group id 0..7
    int tg = lane & 3;           // thread-in-group 0..3

    float c[2][4][4];
#pragma unroll
    for (int mt = 0; mt < 2; mt++)
#pragma unroll
        for (int nt = 0; nt < 4; nt++)
#pragma unroll
            for (int i = 0; i < 4; i++) c[mt][nt][i] = 0.f;

    for (int k0 = 0; k0 < K; k0 += BK) {
        // --- fill As: 128x16 = 512 float4 slots, 2 per thread ---
#pragma unroll
        for (int i = 0; i < 2; i++) {
            int idx = tid + i*256;
            int row = idx >> 2, c4 = (idx & 3) * 4;
            const float* src = &A[(size_t)(m0+row)*K + k0 + c4];
            float4 v = *(const float4*)src;
            As[row][c4+0] = to_tf32(v.x);
            As[row][c4+1] = to_tf32(v.y);
            As[row][c4+2] = to_tf32(v.z);
            As[row][c4+3] = to_tf32(v.w);
        }
        // --- fill Bs: 16x64 = 256 float4 slots, 1 per thread (N guarded) ---
        {
            int row = tid >> 4, c4 = (tid & 15) * 4;
            int gn = n0 + c4;
            if (gn + 3 < N) {
                float4 v = *(const float4*)&B[(size_t)(k0+row)*N + gn];
                Bs[row][c4+0] = to_tf32(v.x);
                Bs[row][c4+1] = to_tf32(v.y);
                Bs[row][c4+2] = to_tf32(v.z);
                Bs[row][c4+3] = to_tf32(v.w);
            } else {
#pragma unroll
                for (int j = 0; j < 4; j++)
                    Bs[row][c4+j] = (gn+j < N) ? to_tf32(B[(size_t)(k0+row)*N + gn+j]) : 0.f;
            }
        }
        __syncthreads();

#pragma unroll
        for (int s = 0; s < BK; s += 8) {
            // A fragments: 2 m16 tiles
            unsigned a[2][4];
#pragma unroll
            for (int mt = 0; mt < 2; mt++) {
                int r0 = wy*32 + mt*16 + g;
                a[mt][0] = __float_as_uint(As[r0    ][s + tg    ]);
                a[mt][1] = __float_as_uint(As[r0 + 8][s + tg    ]);
                a[mt][2] = __float_as_uint(As[r0    ][s + tg + 4]);
                a[mt][3] = __float_as_uint(As[r0 + 8][s + tg + 4]);
            }
            // B fragments: 4 n8 tiles
            unsigned b[4][2];
#pragma unroll
            for (int nt = 0; nt < 4; nt++) {
                int cb = wx*32 + nt*8 + g;
                b[nt][0] = __float_as_uint(Bs[s + tg    ][cb]);
                b[nt][1] = __float_as_uint(Bs[s + tg + 4][cb]);
            }
#pragma unroll
            for (int mt = 0; mt < 2; mt++)
#pragma unroll
                for (int nt = 0; nt < 4; nt++) {
                    asm volatile(
                        "mma.sync.aligned.m16n8k8.row.col.f32.tf32.tf32.f32 "
                        "{%0,%1,%2,%3}, {%4,%5,%6,%7}, {%8,%9}, {%0,%1,%2,%3};\n"
                        : "+f"(c[mt][nt][0]), "+f"(c[mt][nt][1]),
                          "+f"(c[mt][nt][2]), "+f"(c[mt][nt][3])
                        : "r"(a[mt][0]), "r"(a[mt][1]), "r"(a[mt][2]), "r"(a[mt][3]),
                          "r"(b[nt][0]), "r"(b[nt][1]));
                }
        }
        __syncthreads();
    }

    // --- epilogue ---
#pragma unroll
    for (int mt = 0; mt < 2; mt++) {
        int row0 = m0 + wy*32 + mt*16 + g;
#pragma unroll
        for (int nt = 0; nt < 4; nt++) {
            int col = n0 + wx*32 + nt*8 + tg*2;
            if (col >= N) continue;
#pragma unroll
            for (int half = 0; half < 2; half++) {
                int r = row0 + half*8;
                float v0 = c[mt][nt][half*2+0] + bias[col];
                float v1 = c[mt][nt][half*2+1] + bias[col+1];
                if (mode == 1) {
                    v0 += residual[(size_t)r*N + col];
                    v1 += residual[(size_t)r*N + col + 1];
                } else if (mode == 2) {
                    v0 = gelu_tanh(v0);
                    v1 = gelu_tanh(v1);
                }
                float2 out = make_float2(v0, v1);
                *(float2*)&C[(size_t)r*N + col] = out;
            }
        }
    }
}

// ---------------- RoPE: in-place on q and k sections of qkv ----------------
__global__ void rope_kernel(float* __restrict__ qkv, const float* __restrict__ fc) {
    int idx = blockIdx.x * blockDim.x + threadIdx.x;
    const int PER = S_TOK * NH * (HD/2);
    if (idx >= 2*PER) return;
    int which = idx / PER;
    int r = idx - which*PER;
    int s = r / (NH*(HD/2));
    int rem = r - s*(NH*(HD/2));
    int h = rem / (HD/2);
    int i = rem - h*(HD/2);
    size_t base = (size_t)s*QKV_N + which*HID + h*HD + 2*i;
    float c  = fc[((size_t)s*(HD/2) + i)*2 + 0];
    float sn = fc[((size_t)s*(HD/2) + i)*2 + 1];
    float a = qkv[base], b = qkv[base+1];
    qkv[base]   = a*c - b*sn;
    qkv[base+1] = a*sn + b*c;
}

// ---------------- Fused flash-style attention (fp32 SIMT) ----------------
#define AQ 64
#define AK 64
#define QKS 68
#define VS 80

__device__ __forceinline__ int seg_of(int t, const int* offs) {
    int s = 0;
#pragma unroll
    for (int i = 1; i <= 6; i++) if (offs[i] <= t) s = i;
    return s;
}

__global__ void __launch_bounds__(256)
attn_kernel(const float* __restrict__ qkv, const int* __restrict__ offs,
            float* __restrict__ out) {
    extern __shared__ float sm[];
    float* Qs = sm;
    float* Ks = Qs + HD*QKS;
    float* Vs = Ks + HD*QKS;
    float* Ps = Vs + AK*VS;
    int*  segq = (int*)(Ps + AQ*QKS);
    int*  segk = segq + AQ;

    int h = blockIdx.y;
    int q0 = blockIdx.x * AQ;
    int tid = threadIdx.x;
    int tx = tid & 15, ty = tid >> 4;

    for (int l = tid; l < AQ*HD; l += 256) {
        int r = l / HD, d = l - r*HD;
        Qs[d*QKS + r] = qkv[(size_t)(q0+r)*QKV_N + h*HD + d];
    }
    if (tid < AQ) segq[tid] = seg_of(q0 + tid, offs);

    float m_i[4], l_i[4], O[4][5];
#pragma unroll
    for (int i = 0; i < 4; i++) {
        m_i[i] = -1e30f; l_i[i] = 0.f;
#pragma unroll
        for (int jj = 0; jj < 5; jj++) O[i][jj] = 0.f;
    }
    const float scale = 0.11785113019775793f;

    for (int j0 = 0; j0 < S_TOK; j0 += AK) {
        __syncthreads();
        for (int l = tid; l < AK*HD; l += 256) {
            int c = l / HD, d = l - c*HD;
            Ks[d*QKS + c] = qkv[(size_t)(j0+c)*QKV_N + HID + h*HD + d];
        }
        for (int l = tid; l < AK*VS; l += 256) {
            int c = l / VS, d = l - c*VS;
            Vs[l] = (d < HD) ? qkv[(size_t)(j0+c)*QKV_N + 2*HID + h*HD + d] : 0.f;
        }
        if (tid < AK) segk[tid] = seg_of(j0 + tid, offs);
        __syncthreads();

        float s[4][4];
#pragma unroll
        for (int i = 0; i < 4; i++)
#pragma unroll
            for (int j = 0; j < 4; j++) s[i][j] = 0.f;
#pragma unroll 4
        for (int d = 0; d < HD; d++) {
            float4 qa = *(const float4*)&Qs[d*QKS + ty*4];
            float4 kb = *(const float4*)&Ks[d*QKS + tx*4];
            float a[4] = {qa.x,qa.y,qa.z,qa.w};
            float b[4] = {kb.x,kb.y,kb.z,kb.w};
#pragma unroll
            for (int i = 0; i < 4; i++)
#pragma unroll
                for (int j = 0; j < 4; j++) s[i][j] = fmaf(a[i], b[j], s[i][j]);
        }
#pragma unroll
        for (int i = 0; i < 4; i++) {
            int sq = segq[ty*4+i];
#pragma unroll
            for (int j = 0; j < 4; j++)
                s[i][j] = s[i][j]*scale + ((sq == segk[tx*4+j]) ? 1.0f : 0.0f);
        }
#pragma unroll
        for (int i = 0; i < 4; i++) {
            float rmax = fmaxf(fmaxf(s[i][0], s[i][1]), fmaxf(s[i][2], s[i][3]));
#pragma unroll
            for (int o = 8; o > 0; o >>= 1)
                rmax = fmaxf(rmax, __shfl_xor_sync(0xffffffffu, rmax, o, 16));
            float mnew = fmaxf(m_i[i], rmax);
            float fac = __expf(m_i[i] - mnew);
            float psum = 0.f;
#pragma unroll
            for (int j = 0; j < 4; j++) {
                float p = __expf(s[i][j] - mnew);
                s[i][j] = p; psum += p;
            }
#pragma unroll
            for (int o = 8; o > 0; o >>= 1)
                psum += __shfl_xor_sync(0xffffffffu, psum, o, 16);
            l_i[i] = l_i[i]*fac + psum;
            m_i[i] = mnew;
#pragma unroll
            for (int jj = 0; jj < 5; jj++) O[i][jj] *= fac;
        }
#pragma unroll
        for (int i = 0; i < 4; i++)
#pragma unroll
            for (int j = 0; j < 4; j++)
                Ps[(ty*4+i)*QKS + tx*4 + j] = s[i][j];
        __syncthreads();
        for (int kk4 = 0; kk4 < AK; kk4 += 4) {
            float4 p4[4];
#pragma unroll
            for (int i = 0; i < 4; i++)
                p4[i] = *(const float4*)&Ps[(ty*4+i)*QKS + kk4];
#pragma unroll
            for (int u = 0; u < 4; u++) {
                int kk = kk4 + u;
                float v[5];
#pragma unroll
                for (int jj = 0; jj < 5; jj++) v[jj] = Vs[kk*VS + tx + 16*jj];
                float pv[4] = {
                    (u==0)?p4[0].x:(u==1)?p4[0].y:(u==2)?p4[0].z:p4[0].w,
                    (u==0)?p4[1].x:(u==1)?p4[1].y:(u==2)?p4[1].z:p4[1].w,
                    (u==0)?p4[2].x:(u==1)?p4[2].y:(u==2)?p4[2].z:p4[2].w,
                    (u==0)?p4[3].x:(u==1)?p4[3].y:(u==2)?p4[3].z:p4[3].w };
#pragma unroll
                for (int i = 0; i < 4; i++)
#pragma unroll
                    for (int jj = 0; jj < 5; jj++)
                        O[i][jj] = fmaf(pv[i], v[jj], O[i][jj]);
            }
        }
    }
#pragma unroll
    for (int i = 0; i < 4; i++) {
        float inv = 1.0f / l_i[i];
        int r = q0 + ty*4 + i;
#pragma unroll
        for (int jj = 0; jj < 5; jj++) {
            int d = tx + 16*jj;
            if (d < HD)
                out[(size_t)r*HID + h*HD + d] = O[i][jj] * inv;
        }
    }
}

// ---------------- launch ----------------
extern "C" void kernel_launch(void* const* d_in, const int* in_sizes, int n_in,
                              void* d_out, int out_size) {
    const float* x      = (const float*)d_in[0];
    const int*   offs   = (const int*)  d_in[1];
    const float* fc     = (const float*)d_in[2];
    const float* ln0_g  = (const float*)d_in[3];
    const float* ln0_b  = (const float*)d_in[4];
    const float* wqkv_w = (const float*)d_in[5];
    const float* wqkv_b = (const float*)d_in[6];
    const float* wo_w   = (const float*)d_in[7];
    const float* wo_b   = (const float*)d_in[8];
    const float* ln1_g  = (const float*)d_in[9];
    const float* ln1_b  = (const float*)d_in[10];
    const float* w1     = (const float*)d_in[11];
    const float* b1     = (const float*)d_in[12];
    const float* w2     = (const float*)d_in[13];
    const float* b2     = (const float*)d_in[14];
    float* out = (float*)d_out;

    float *h0, *qkv, *attn, *x2, *h1, *mlp;
    cudaGetSymbolAddress((void**)&h0,   g_h0);
    cudaGetSymbolAddress((void**)&qkv,  g_qkv);
    cudaGetSymbolAddress((void**)&attn, g_attn);
    cudaGetSymbolAddress((void**)&x2,   g_x2);
    cudaGetSymbolAddress((void**)&h1,   g_h1);
    cudaGetSymbolAddress((void**)&mlp,  g_mlp);

    const int ATTN_SMEM = (HD*QKS + HD*QKS + AK*VS + AQ*QKS) * 4 + 2*AQ*4;
    cudaFuncSetAttribute(attn_kernel, cudaFuncAttributeMaxDynamicSharedMemorySize, ATTN_SMEM);

    // 1. LN0
    ln_kernel<<<S_TOK, 256>>>(x, ln0_g, ln0_b, h0);
    // 2. QKV = h0 @ wqkv + b
    mma_gemm_kernel<<<dim3(QKV_N/BN, S_TOK/BM), 256>>>(h0, wqkv_w, wqkv_b, nullptr, qkv,
                                                       S_TOK, QKV_N, HID, 0);
    // 3. RoPE on q,k
    {
        int total = 2 * S_TOK * NH * (HD/2);
        rope_kernel<<<(total + 255)/256, 256>>>(qkv, fc);
    }
    // 4. attention
    attn_kernel<<<dim3(S_TOK/AQ, NH), 256, ATTN_SMEM>>>(qkv, offs, attn);
    // 5. x2 = x + attn @ wo + b
    mma_gemm_kernel<<<dim3(HID/BN, S_TOK/BM), 256>>>(attn, wo_w, wo_b, x, x2,
                                                     S_TOK, HID, HID, 1);
    // 6. LN1
    ln_kernel<<<S_TOK, 256>>>(x2, ln1_g, ln1_b, h1);
    // 7. mlp = gelu(h1 @ w1 + b1)
    mma_gemm_kernel<<<dim3((MLP_DIM+BN-1)/BN, S_TOK/BM), 256>>>(h1, w1, b1, nullptr, mlp,
                                                                S_TOK, MLP_DIM, HID, 2);
    // 8. out = x2 + mlp @ w2 + b2
    mma_gemm_kernel<<<dim3(HID/BN, S_TOK/BM), 256>>>(mlp, w2, b2, x2, out,
                                                     S_TOK, HID, MLP_DIM, 1);
}

// round 3
// speedup vs baseline: 2.0005x; 1.3136x over previous
#include <cuda_runtime.h>
#include <cuda_bf16.h>
#include <math.h>

// Problem constants
#define S_TOK 3072
#define HID 1152
#define NH 16
#define HD 72
#define MLP_DIM 4304
#define QKV_N (3*HID)   // 3456
#define EPS 1e-5f

// ---------------- scratch (allocation-free: __device__ globals) ----------------
__device__ float g_h0[S_TOK*HID];
__device__ float g_qkv[S_TOK*QKV_N];
__device__ float g_attn[S_TOK*HID];
__device__ float g_x2[S_TOK*HID];
__device__ float g_h1[S_TOK*HID];
__device__ float g_mlp[S_TOK*MLP_DIM];

// ---------------- LayerNorm ----------------
__global__ void ln_kernel(const float* __restrict__ x, const float* __restrict__ g,
                          const float* __restrict__ b, float* __restrict__ y) {
    __shared__ float row[HID];
    __shared__ float red_s[256], red_ss[256];
    int r = blockIdx.x;
    int tid = threadIdx.x;
    float s = 0.f, ss = 0.f;
    for (int i = tid; i < HID; i += 256) {
        float v = x[(size_t)r*HID + i];
        row[i] = v;
        s += v; ss += v*v;
    }
    red_s[tid] = s; red_ss[tid] = ss;
    __syncthreads();
    for (int o = 128; o > 0; o >>= 1) {
        if (tid < o) { red_s[tid] += red_s[tid+o]; red_ss[tid] += red_ss[tid+o]; }
        __syncthreads();
    }
    float mu = red_s[0] * (1.0f/HID);
    float var = red_ss[0] * (1.0f/HID) - mu*mu;
    float rstd = rsqrtf(var + EPS);
    for (int i = tid; i < HID; i += 256) {
        y[(size_t)r*HID + i] = (row[i] - mu) * rstd * g[i] + b[i];
    }
}

// ---------------- helpers ----------------
__device__ __forceinline__ float gelu_tanh(float v) {
    float c = 0.7978845608028654f * (v + 0.044715f * v * v * v);
    return 0.5f * v * (1.0f + tanhf(c));
}
__device__ __forceinline__ float to_tf32(float x) {
    unsigned r;
    asm("cvt.rna.tf32.f32 %0, %1;" : "=r"(r) : "f"(x));
    return __uint_as_float(r);
}
#define MMA_TF32(C, A, B0, B1)                                            \
    asm volatile("mma.sync.aligned.m16n8k8.row.col.f32.tf32.tf32.f32 "    \
                 "{%0,%1,%2,%3}, {%4,%5,%6,%7}, {%8,%9}, {%0,%1,%2,%3};\n"\
                 : "+f"(C[0]), "+f"(C[1]), "+f"(C[2]), "+f"(C[3])         \
                 : "r"(A[0]), "r"(A[1]), "r"(A[2]), "r"(A[3]),            \
                   "r"(B0), "r"(B1))

// ---------------- tf32 tensor-core GEMM (unchanged from R2) ----------------
#define BM 128
#define BN 64
#define BK 16
#define AST 20
#define BST 72

__global__ void __launch_bounds__(256)
mma_gemm_kernel(const float* __restrict__ A, const float* __restrict__ B,
                const float* __restrict__ bias, const float* __restrict__ residual,
                float* __restrict__ C, int M, int N, int K, int mode) {
    __shared__ float As[BM][AST];
    __shared__ float Bs[BK][BST];

    int tid  = threadIdx.x;
    int warp = tid >> 5;
    int lane = tid & 31;
    int wy = warp >> 1, wx = warp & 1;
    int m0 = blockIdx.y * BM;
    int n0 = blockIdx.x * BN;
    int g  = lane >> 2, tg = lane & 3;

    float c[2][4][4];
#pragma unroll
    for (int mt = 0; mt < 2; mt++)
#pragma unroll
        for (int nt = 0; nt < 4; nt++)
#pragma unroll
            for (int i = 0; i < 4; i++) c[mt][nt][i] = 0.f;

    for (int k0 = 0; k0 < K; k0 += BK) {
#pragma unroll
        for (int i = 0; i < 2; i++) {
            int idx = tid + i*256;
            int row = idx >> 2, c4 = (idx & 3) * 4;
            float4 v = *(const float4*)&A[(size_t)(m0+row)*K + k0 + c4];
            As[row][c4+0] = to_tf32(v.x);
            As[row][c4+1] = to_tf32(v.y);
            As[row][c4+2] = to_tf32(v.z);
            As[row][c4+3] = to_tf32(v.w);
        }
        {
            int row = tid >> 4, c4 = (tid & 15) * 4;
            int gn = n0 + c4;
            if (gn + 3 < N) {
                float4 v = *(const float4*)&B[(size_t)(k0+row)*N + gn];
                Bs[row][c4+0] = to_tf32(v.x);
                Bs[row][c4+1] = to_tf32(v.y);
                Bs[row][c4+2] = to_tf32(v.z);
                Bs[row][c4+3] = to_tf32(v.w);
            } else {
#pragma unroll
                for (int j = 0; j < 4; j++)
                    Bs[row][c4+j] = (gn+j < N) ? to_tf32(B[(size_t)(k0+row)*N + gn+j]) : 0.f;
            }
        }
        __syncthreads();

#pragma unroll
        for (int s = 0; s < BK; s += 8) {
            unsigned a[2][4];
#pragma unroll
            for (int mt = 0; mt < 2; mt++) {
                int r0 = wy*32 + mt*16 + g;
                a[mt][0] = __float_as_uint(As[r0    ][s + tg    ]);
                a[mt][1] = __float_as_uint(As[r0 + 8][s + tg    ]);
                a[mt][2] = __float_as_uint(As[r0    ][s + tg + 4]);
                a[mt][3] = __float_as_uint(As[r0 + 8][s + tg + 4]);
            }
            unsigned b[4][2];
#pragma unroll
            for (int nt = 0; nt < 4; nt++) {
                int cb = wx*32 + nt*8 + g;
                b[nt][0] = __float_as_uint(Bs[s + tg    ][cb]);
                b[nt][1] = __float_as_uint(Bs[s + tg + 4][cb]);
            }
#pragma unroll
            for (int mt = 0; mt < 2; mt++)
#pragma unroll
                for (int nt = 0; nt < 4; nt++)
                    MMA_TF32(c[mt][nt], a[mt], b[nt][0], b[nt][1]);
        }
        __syncthreads();
    }

#pragma unroll
    for (int mt = 0; mt < 2; mt++) {
        int row0 = m0 + wy*32 + mt*16 + g;
#pragma unroll
        for (int nt = 0; nt < 4; nt++) {
            int col = n0 + wx*32 + nt*8 + tg*2;
            if (col >= N) continue;
#pragma unroll
            for (int half = 0; half < 2; half++) {
                int r = row0 + half*8;
                float v0 = c[mt][nt][half*2+0] + bias[col];
                float v1 = c[mt][nt][half*2+1] + bias[col+1];
                if (mode == 1) {
                    v0 += residual[(size_t)r*N + col];
                    v1 += residual[(size_t)r*N + col + 1];
                } else if (mode == 2) {
                    v0 = gelu_tanh(v0);
                    v1 = gelu_tanh(v1);
                }
                *(float2*)&C[(size_t)r*N + col] = make_float2(v0, v1);
            }
        }
    }
}

// ---------------- RoPE ----------------
__global__ void rope_kernel(float* __restrict__ qkv, const float* __restrict__ fc) {
    int idx = blockIdx.x * blockDim.x + threadIdx.x;
    const int PER = S_TOK * NH * (HD/2);
    if (idx >= 2*PER) return;
    int which = idx / PER;
    int r = idx - which*PER;
    int s = r / (NH*(HD/2));
    int rem = r - s*(NH*(HD/2));
    int h = rem / (HD/2);
    int i = rem - h*(HD/2);
    size_t base = (size_t)s*QKV_N + which*HID + h*HD + 2*i;
    float c  = fc[((size_t)s*(HD/2) + i)*2 + 0];
    float sn = fc[((size_t)s*(HD/2) + i)*2 + 1];
    float a = qkv[base], b = qkv[base+1];
    qkv[base]   = a*c - b*sn;
    qkv[base+1] = a*sn + b*c;
}

// ---------------- tensor-core flash attention ----------------
// Block: 64 q-rows x 1 head, 256 threads (8 warps).
// S = Q K^T via mma; online softmax; O += P V via mma.
#define AQ 64
#define AK 64
#define QST 76    // Qs [64 r][72 d]    : ((76g+tg)%32 distinct)
#define KST 68    // Ks [72 d][64 c]    : ((68tg+g)%32 distinct)
#define VST 100   // Vs [64 tok][96 d]  : ((100tg+g)%32 distinct)
#define PST 68    // Ps [64 r][64 c]    : ((68g+tg)%32 distinct)
#define VPAD 96

__device__ __forceinline__ int seg_of(int t, const int* offs) {
    int s = 0;
#pragma unroll
    for (int i = 1; i <= 6; i++) if (offs[i] <= t) s = i;
    return s;
}

__global__ void __launch_bounds__(256)
attn_kernel(const float* __restrict__ qkv, const int* __restrict__ offs,
            float* __restrict__ out) {
    extern __shared__ float sm[];
    float* Qs   = sm;                  // 64*76
    float* Ks   = Qs + AQ*QST;         // 72*68
    float* Vs   = Ks + HD*KST;         // 64*100 (cols 72..95 zero)
    float* Ps   = Vs + AK*VST;         // 64*68
    float* fac  = Ps + AQ*PST;         // 64
    float* lsum = fac + 64;            // 64
    int* segq = (int*)(lsum + 64);     // 64
    int* segk = segq + 64;             // 64

    int h = blockIdx.y;
    int q0 = blockIdx.x * AQ;
    int tid = threadIdx.x;
    int warp = tid >> 5, lane = tid & 31;
    int g = lane >> 2, tg = lane & 3;
    int wy = warp >> 1, wx = warp & 1;

    // load Q (tf32-rounded)
    for (int l = tid; l < AQ*HD; l += 256) {
        int r = l / HD, d = l - r*HD;
        Qs[r*QST + d] = to_tf32(qkv[(size_t)(q0+r)*QKV_N + h*HD + d]);
    }
    if (tid < AQ) segq[tid] = seg_of(q0 + tid, offs);

    // softmax row ownership: row = tid>>2, 4 lanes x 16 cols
    int srow = tid >> 2, spart = tid & 3;
    float m_i = -1e30f, l_i = 0.f;

    float c_o[6][4];
#pragma unroll
    for (int nt = 0; nt < 6; nt++)
#pragma unroll
        for (int i = 0; i < 4; i++) c_o[nt][i] = 0.f;

    const float scale = 0.11785113019775793f;  // 1/sqrt(72)
    const int r1 = wy*16 + g, r2 = r1 + 8;

    for (int j0 = 0; j0 < S_TOK; j0 += AK) {
        __syncthreads();  // protect Ks/Vs/Ps from overwrite
        // load K transposed [d][c]
        for (int l = tid; l < AK*HD; l += 256) {
            int c = l / HD, d = l - c*HD;
            Ks[d*KST + c] = to_tf32(qkv[(size_t)(j0+c)*QKV_N + HID + h*HD + d]);
        }
        // load V [tok][d], pad d to 96 with zeros
        for (int l = tid; l < AK*VPAD; l += 256) {
            int c = l / VPAD, d = l - c*VPAD;
            Vs[c*VST + d] = (d < HD) ? qkv[(size_t)(j0+c)*QKV_N + 2*HID + h*HD + d] : 0.f;
        }
        if (tid < AK) segk[tid] = seg_of(j0 + tid, offs);
        __syncthreads();

        // --- S = Q K^T : warp (wy,wx) -> rows wy*16..+16, cols wx*32..+32 ---
        float sc[4][4];
#pragma unroll
        for (int nt = 0; nt < 4; nt++)
#pragma unroll
            for (int i = 0; i < 4; i++) sc[nt][i] = 0.f;
#pragma unroll
        for (int s = 0; s < 72; s += 8) {
            unsigned a[4];
            a[0] = __float_as_uint(Qs[r1*QST + s + tg    ]);
            a[1] = __float_as_uint(Qs[r2*QST + s + tg    ]);
            a[2] = __float_as_uint(Qs[r1*QST + s + tg + 4]);
            a[3] = __float_as_uint(Qs[r2*QST + s + tg + 4]);
#pragma unroll
            for (int nt = 0; nt < 4; nt++) {
                int cb = wx*32 + nt*8 + g;
                unsigned b0 = __float_as_uint(Ks[(s + tg    )*KST + cb]);
                unsigned b1 = __float_as_uint(Ks[(s + tg + 4)*KST + cb]);
                MMA_TF32(sc[nt], a, b0, b1);
            }
        }
        // epilogue: scale + segment bias, stage to Ps
        {
            int sq1 = segq[r1], sq2 = segq[r2];
#pragma unroll
            for (int nt = 0; nt < 4; nt++) {
                int col = wx*32 + nt*8 + tg*2;
                int sk0 = segk[col], sk1 = segk[col+1];
                Ps[r1*PST + col    ] = sc[nt][0]*scale + ((sq1==sk0) ? 1.f : 0.f);
                Ps[r1*PST + col + 1] = sc[nt][1]*scale + ((sq1==sk1) ? 1.f : 0.f);
                Ps[r2*PST + col    ] = sc[nt][2]*scale + ((sq2==sk0) ? 1.f : 0.f);
                Ps[r2*PST + col + 1] = sc[nt][3]*scale + ((sq2==sk1) ? 1.f : 0.f);
            }
        }
        __syncthreads();

        // --- online softmax on Ps rows ---
        {
            float* prow = &Ps[srow*PST + spart*16];
            float v[16];
            float mx = -1e30f;
#pragma unroll
            for (int j = 0; j < 16; j++) { v[j] = prow[j]; mx = fmaxf(mx, v[j]); }
            mx = fmaxf(mx, __shfl_xor_sync(0xffffffffu, mx, 1, 4));
            mx = fmaxf(mx, __shfl_xor_sync(0xffffffffu, mx, 2, 4));
            float mnew = fmaxf(m_i, mx);
            float f = __expf(m_i - mnew);
            float ps = 0.f;
#pragma unroll
            for (int j = 0; j < 16; j++) {
                v[j] = __expf(v[j] - mnew);
                ps += v[j];
                prow[j] = v[j];
            }
            ps += __shfl_xor_sync(0xffffffffu, ps, 1, 4);
            ps += __shfl_xor_sync(0xffffffffu, ps, 2, 4);
            l_i = l_i*f + ps;
            m_i = mnew;
            if (spart == 0) fac[srow] = f;
        }
        __syncthreads();

        // --- rescale O, then O += P V : warp covers rows wy*16..+16, d-cols wx*48..+48 ---
        {
            float f1 = fac[r1], f2 = fac[r2];
#pragma unroll
            for (int nt = 0; nt < 6; nt++) {
                c_o[nt][0] *= f1; c_o[nt][1] *= f1;
                c_o[nt][2] *= f2; c_o[nt][3] *= f2;
            }
        }
#pragma unroll
        for (int s = 0; s < AK; s += 8) {
            unsigned a[4];
            a[0] = __float_as_uint(Ps[r1*PST + s + tg    ]);
            a[1] = __float_as_uint(Ps[r2*PST + s + tg    ]);
            a[2] = __float_as_uint(Ps[r1*PST + s + tg + 4]);
            a[3] = __float_as_uint(Ps[r2*PST + s + tg + 4]);
#pragma unroll
            for (int nt = 0; nt < 6; nt++) {
                int cb = wx*48 + nt*8 + g;
                unsigned b0 = __float_as_uint(Vs[(s + tg    )*VST + cb]);
                unsigned b1 = __float_as_uint(Vs[(s + tg + 4)*VST + cb]);
                MMA_TF32(c_o[nt], a, b0, b1);
            }
        }
    }

    // --- final normalize + store ---
    if (spart == 0) lsum[srow] = l_i;
    __syncthreads();
    float i1 = 1.0f / lsum[r1], i2 = 1.0f / lsum[r2];
#pragma unroll
    for (int nt = 0; nt < 6; nt++) {
        int d0 = wx*48 + nt*8 + tg*2;
        if (d0 < HD) {
            *(float2*)&out[(size_t)(q0+r1)*HID + h*HD + d0] =
                make_float2(c_o[nt][0]*i1, c_o[nt][1]*i1);
            *(float2*)&out[(size_t)(q0+r2)*HID + h*HD + d0] =
                make_float2(c_o[nt][2]*i2, c_o[nt][3]*i2);
        }
    }
}

// ---------------- launch ----------------
extern "C" void kernel_launch(void* const* d_in, const int* in_sizes, int n_in,
                              void* d_out, int out_size) {
    const float* x      = (const float*)d_in[0];
    const int*   offs   = (const int*)  d_in[1];
    const float* fc     = (const float*)d_in[2];
    const float* ln0_g  = (const float*)d_in[3];
    const float* ln0_b  = (const float*)d_in[4];
    const float* wqkv_w = (const float*)d_in[5];
    const float* wqkv_b = (const float*)d_in[6];
    const float* wo_w   = (const float*)d_in[7];
    const float* wo_b   = (const float*)d_in[8];
    const float* ln1_g  = (const float*)d_in[9];
    const float* ln1_b  = (const float*)d_in[10];
    const float* w1     = (const float*)d_in[11];
    const float* b1     = (const float*)d_in[12];
    const float* w2     = (const float*)d_in[13];
    const float* b2     = (const float*)d_in[14];
    float* out = (float*)d_out;

    float *h0, *qkv, *attn, *x2, *h1, *mlp;
    cudaGetSymbolAddress((void**)&h0,   g_h0);
    cudaGetSymbolAddress((void**)&qkv,  g_qkv);
    cudaGetSymbolAddress((void**)&attn, g_attn);
    cudaGetSymbolAddress((void**)&x2,   g_x2);
    cudaGetSymbolAddress((void**)&h1,   g_h1);
    cudaGetSymbolAddress((void**)&mlp,  g_mlp);

    const int ATTN_SMEM = (AQ*QST + HD*KST + AK*VST + AQ*PST + 64 + 64) * 4 + 2*64*4;
    cudaFuncSetAttribute(attn_kernel, cudaFuncAttributeMaxDynamicSharedMemorySize, ATTN_SMEM);

    // 1. LN0
    ln_kernel<<<S_TOK, 256>>>(x, ln0_g, ln0_b, h0);
    // 2. QKV = h0 @ wqkv + b
    mma_gemm_kernel<<<dim3(QKV_N/BN, S_TOK/BM), 256>>>(h0, wqkv_w, wqkv_b, nullptr, qkv,
                                                       S_TOK, QKV_N, HID, 0);
    // 3. RoPE on q,k
    {
        int total = 2 * S_TOK * NH * (HD/2);
        rope_kernel<<<(total + 255)/256, 256>>>(qkv, fc);
    }
    // 4. attention (tensor-core)
    attn_kernel<<<dim3(S_TOK/AQ, NH), 256, ATTN_SMEM>>>(qkv, offs, attn);
    // 5. x2 = x + attn @ wo + b
    mma_gemm_kernel<<<dim3(HID/BN, S_TOK/BM), 256>>>(attn, wo_w, wo_b, x, x2,
                                                     S_TOK, HID, HID, 1);
    // 6. LN1
    ln_kernel<<<S_TOK, 256>>>(x2, ln1_g, ln1_b, h1);
    // 7. mlp = gelu(h1 @ w1 + b1)
    mma_gemm_kernel<<<dim3((MLP_DIM+BN-1)/BN, S_TOK/BM), 256>>>(h1, w1, b1, nullptr, mlp,
                                                                S_TOK, MLP_DIM, HID, 2);
    // 8. out = x2 + mlp @ w2 + b2
    mma_gemm_kernel<<<dim3(HID/BN, S_TOK/BM), 256>>>(mlp, w2, b2, x2, out,
                                                     S_TOK, HID, MLP_DIM, 1);
}

// round 6
// speedup vs baseline: 2.7032x; 1.3513x over previous
#include <cuda_runtime.h>
#include <cuda_bf16.h>
#include <math.h>

// Problem constants
#define S_TOK 3072
#define HID 1152
#define NH 16
#define HD 72
#define MLP_DIM 4304
#define QKV_N (3*HID)   // 3456
#define EPS 1e-5f

// ---------------- scratch (allocation-free: __device__ globals) ----------------
__device__ float g_h0[S_TOK*HID];
__device__ float g_qkv[S_TOK*QKV_N];
__device__ float g_attn[S_TOK*HID];
__device__ float g_x2[S_TOK*HID];
__device__ float g_h1[S_TOK*HID];
__device__ float g_mlp[S_TOK*MLP_DIM];
// transposed weights [N][K] (tf32-rounded)
__device__ float g_wqkvt[QKV_N*HID];
__device__ float g_wot[HID*HID];
__device__ float g_w1t[MLP_DIM*HID];
__device__ float g_w2t[HID*MLP_DIM];

// ---------------- PTX helpers ----------------
#define MMA_TF32(C, A, B0, B1)                                            \
    asm volatile("mma.sync.aligned.m16n8k8.row.col.f32.tf32.tf32.f32 "    \
                 "{%0,%1,%2,%3}, {%4,%5,%6,%7}, {%8,%9}, {%0,%1,%2,%3};\n"\
                 : "+f"((C)[0]), "+f"((C)[1]), "+f"((C)[2]), "+f"((C)[3]) \
                 : "r"((A)[0]), "r"((A)[1]), "r"((A)[2]), "r"((A)[3]),    \
                   "r"(B0), "r"(B1))

#define LDSM_X4(R, a)                                                          \
    asm volatile("ldmatrix.sync.aligned.m8n8.x4.shared.b16 {%0,%1,%2,%3}, [%4];" \
                 : "=r"((R)[0]), "=r"((R)[1]), "=r"((R)[2]), "=r"((R)[3])      \
                 : "r"(a))
#define LDSM_X2(R, a)                                                          \
    asm volatile("ldmatrix.sync.aligned.m8n8.x2.shared.b16 {%0,%1}, [%2];"     \
                 : "=r"((R)[0]), "=r"((R)[1]) : "r"(a))

__device__ __forceinline__ void cp_async16(unsigned dst, const void* src, bool valid) {
    int sz = valid ? 16 : 0;
    asm volatile("cp.async.cg.shared.global [%0], [%1], 16, %2;"
                 :: "r"(dst), "l"(src), "r"(sz));
}
#define CP_COMMIT asm volatile("cp.async.commit_group;")
#define CP_WAIT1  asm volatile("cp.async.wait_group 1;")

__device__ __forceinline__ float gelu_tanh(float v) {
    float c = 0.7978845608028654f * (v + 0.044715f * v * v * v);
    return 0.5f * v * (1.0f + tanhf(c));
}
__device__ __forceinline__ float to_tf32(float x) {
    unsigned r;
    asm("cvt.rna.tf32.f32 %0, %1;" : "=r"(r) : "f"(x));
    return __uint_as_float(r);
}

// ---------------- LayerNorm (emits tf32-rounded output: feeds GEMM A) ------
__global__ void ln_kernel(const float* __restrict__ x, const float* __restrict__ g,
                          const float* __restrict__ b, float* __restrict__ y) {
    __shared__ float row[HID];
    __shared__ float red_s[256], red_ss[256];
    int r = blockIdx.x;
    int tid = threadIdx.x;
    float s = 0.f, ss = 0.f;
    for (int i = tid; i < HID; i += 256) {
        float v = x[(size_t)r*HID + i];
        row[i] = v;
        s += v; ss += v*v;
    }
    red_s[tid] = s; red_ss[tid] = ss;
    __syncthreads();
    for (int o = 128; o > 0; o >>= 1) {
        if (tid < o) { red_s[tid] += red_s[tid+o]; red_ss[tid] += red_ss[tid+o]; }
        __syncthreads();
    }
    float mu = red_s[0] * (1.0f/HID);
    float var = red_ss[0] * (1.0f/HID) - mu*mu;
    float rstd = rsqrtf(var + EPS);
    for (int i = tid; i < HID; i += 256) {
        y[(size_t)r*HID + i] = to_tf32((row[i] - mu) * rstd * g[i] + b[i]);
    }
}

// ---------------- weight transpose: [K][N] -> [N][K], tf32-rounded ----------
__global__ void transpose_kernel(const float* __restrict__ in, float* __restrict__ out,
                                 int K, int N) {
    __shared__ float t[32][33];
    int kb = blockIdx.y*32, nb = blockIdx.x*32;
    int x = threadIdx.x, y = threadIdx.y;   // 32 x 8
#pragma unroll
    for (int i = 0; i < 32; i += 8) {
        int k = kb + y + i, n = nb + x;
        t[y+i][x] = (k < K && n < N) ? in[(size_t)k*N + n] : 0.f;
    }
    __syncthreads();
#pragma unroll
    for (int i = 0; i < 32; i += 8) {
        int n = nb + y + i, k = kb + x;
        if (n < N && k < K) out[(size_t)n*K + k] = to_tf32(t[x][y+i]);
    }
}

// ---------------- tf32 GEMM: ldmatrix + cp.async double buffer ----------------
// C[M,N] = A[M,K] @ Bt[N,K]^T + bias (+residual/gelu). A,Bt pre-rounded to tf32.
#define GBM 128
#define GBN 128
#define GBK 32
#define GST 36                 // smem row stride (floats)
#define STG_F (GBM*GST)        // 4608 floats per As / Bs tile
#define STAGE_F (2*STG_F)      // 9216 per stage

__global__ void __launch_bounds__(256, 2)
mma_gemm2(const float* __restrict__ A, const float* __restrict__ Bt,
          const float* __restrict__ bias, const float* __restrict__ residual,
          float* __restrict__ C, int M, int N, int K, int NIT, int mode) {
    extern __shared__ float smg[];
    unsigned sbase = (unsigned)__cvta_generic_to_shared(smg);
    int tid = threadIdx.x, warp = tid >> 5, lane = tid & 31;
    int g = lane >> 2, tg = lane & 3;
    int wy = warp >> 1, wx = warp & 1;
    int m0 = blockIdx.y*GBM, n0 = blockIdx.x*GBN;

    float c[2][8][4];
#pragma unroll
    for (int mt = 0; mt < 2; mt++)
#pragma unroll
        for (int nt = 0; nt < 8; nt++)
#pragma unroll
            for (int i = 0; i < 4; i++) c[mt][nt][i] = 0.f;

    auto stage = [&](int it, int buf) {
        int k0 = it*GBK;
        unsigned sA = sbase + buf*STAGE_F*4;
        unsigned sB = sA + STG_F*4;
#pragma unroll
        for (int i = 0; i < 4; i++) {
            int t = tid + i*256;
            int row = t >> 3, ch = t & 7;
            int k = k0 + ch*4;
            bool v = (k < K);
            cp_async16(sA + (row*GST + ch*4)*4,
                       A + (size_t)(m0+row)*K + (v ? k : 0), v);
        }
#pragma unroll
        for (int i = 0; i < 4; i++) {
            int t = tid + i*256;
            int row = t >> 3, ch = t & 7;
            int k = k0 + ch*4;
            int n = n0 + row;
            bool v = (k < K) && (n < N);
            cp_async16(sB + (row*GST + ch*4)*4,
                       Bt + (size_t)(v ? n : 0)*K + (v ? k : 0), v);
        }
    };

    stage(0, 0); CP_COMMIT;

    unsigned offA[2], offB[4];
    {
        int rA = lane & 15, cA = (lane & 16) ? 4 : 0;
#pragma unroll
        for (int mt = 0; mt < 2; mt++)
            offA[mt] = ((wy*32 + mt*16 + rA)*GST + cA)*4;
        int rB = (lane & 7) + ((lane & 16) >> 1);
        int cB = (lane & 8) ? 4 : 0;
#pragma unroll
        for (int p = 0; p < 4; p++)
            offB[p] = ((wx*64 + p*16 + rB)*GST + cB)*4;
    }

    for (int it = 0; it < NIT; it++) {
        int buf = it & 1;
        if (it + 1 < NIT) stage(it+1, buf^1);
        CP_COMMIT;
        CP_WAIT1;
        __syncthreads();
        unsigned sA = sbase + buf*STAGE_F*4;
        unsigned sB = sA + STG_F*4;
#pragma unroll
        for (int s = 0; s < GBK; s += 8) {
            unsigned a[2][4], b[4][4];
            LDSM_X4(a[0], sA + offA[0] + s*4);
            LDSM_X4(a[1], sA + offA[1] + s*4);
#pragma unroll
            for (int p = 0; p < 4; p++) LDSM_X4(b[p], sB + offB[p] + s*4);
#pragma unroll
            for (int mt = 0; mt < 2; mt++)
#pragma unroll
                for (int p = 0; p < 4; p++) {
                    MMA_TF32(c[mt][2*p],   a[mt], b[p][0], b[p][1]);
                    MMA_TF32(c[mt][2*p+1], a[mt], b[p][2], b[p][3]);
                }
        }
        __syncthreads();
    }

    // epilogue
#pragma unroll
    for (int mt = 0; mt < 2; mt++) {
        int row0 = m0 + wy*32 + mt*16 + g;
#pragma unroll
        for (int nt = 0; nt < 8; nt++) {
            int col = n0 + wx*64 + nt*8 + tg*2;
            if (col >= N) continue;
#pragma unroll
            for (int hf = 0; hf < 2; hf++) {
                int r = row0 + hf*8;
                float v0 = c[mt][nt][hf*2+0] + bias[col];
                float v1 = c[mt][nt][hf*2+1] + bias[col+1];
                if (mode == 1) {
                    v0 += residual[(size_t)r*N + col];
                    v1 += residual[(size_t)r*N + col + 1];
                } else if (mode == 2) {
                    v0 = to_tf32(gelu_tanh(v0));   // feeds next GEMM A
                    v1 = to_tf32(gelu_tanh(v1));
                }
                *(float2*)&C[(size_t)r*N + col] = make_float2(v0, v1);
            }
        }
    }
}

// ---------------- RoPE (emits tf32-rounded q,k) ----------------
__global__ void rope_kernel(float* __restrict__ qkv, const float* __restrict__ fc) {
    int idx = blockIdx.x * blockDim.x + threadIdx.x;
    const int PER = S_TOK * NH * (HD/2);
    if (idx >= 2*PER) return;
    int which = idx / PER;
    int r = idx - which*PER;
    int s = r / (NH*(HD/2));
    int rem = r - s*(NH*(HD/2));
    int h = rem / (HD/2);
    int i = rem - h*(HD/2);
    size_t base = (size_t)s*QKV_N + which*HID + h*HD + 2*i;
    float c  = fc[((size_t)s*(HD/2) + i)*2 + 0];
    float sn = fc[((size_t)s*(HD/2) + i)*2 + 1];
    float a = qkv[base], b = qkv[base+1];
    qkv[base]   = to_tf32(a*c - b*sn);
    qkv[base+1] = to_tf32(a*sn + b*c);
}

// ---------------- attention: AQ=128, register softmax, ldmatrix ----------------
#define AQ2 128
#define AK2 64
#define QKST 76    // Qs/Ks row stride
#define VST2 68    // Vs [d][tok] stride
#define PST2 68    // Ps [q][tok] stride

__device__ __forceinline__ int seg_of(int t, const int* offs) {
    int s = 0;
#pragma unroll
    for (int i = 1; i <= 6; i++) if (offs[i] <= t) s = i;
    return s;
}

__global__ void __launch_bounds__(256, 1)
attn2_kernel(const float* __restrict__ qkv, const int* __restrict__ offs,
             float* __restrict__ out) {
    extern __shared__ float sm[];
    float* Qs = sm;                          // 128*76
    float* Ks = Qs + AQ2*QKST;               // 64*76
    float* Vs = Ks + AK2*QKST;               // 72*68
    float* Ps = Vs + HD*VST2;                // 128*68
    int* segk  = (int*)(Ps + AQ2*PST2);      // 64
    int* soffs = segk + 64;                  // 8

    unsigned sbase = (unsigned)__cvta_generic_to_shared(sm);
    unsigned uQ = sbase;
    unsigned uK = sbase + AQ2*QKST*4;
    unsigned uV = uK + AK2*QKST*4;
    unsigned uP = uV + HD*VST2*4;

    int tid = threadIdx.x, warp = tid >> 5, lane = tid & 31;
    int g = lane >> 2, tg = lane & 3;
    int h = blockIdx.y, q0 = blockIdx.x*AQ2;

    if (tid < 7) soffs[tid] = offs[tid];

    // stage Q (tf32 from rope): 128 rows x 18 float4 chunks
    for (int t = tid; t < AQ2*18; t += 256) {
        int row = t/18, ch = t - row*18;
        float4 v = *(const float4*)&qkv[(size_t)(q0+row)*QKV_N + h*HD + ch*4];
        *(float4*)&Qs[row*QKST + ch*4] = v;
    }
    __syncthreads();

    int r1 = warp*16 + g, r2 = r1 + 8;
    int sq1 = seg_of(q0 + r1, soffs);
    int sq2 = seg_of(q0 + r2, soffs);

    float m1 = -1e30f, m2 = -1e30f, l1 = 0.f, l2 = 0.f;
    float co[9][4];
#pragma unroll
    for (int nt = 0; nt < 9; nt++)
#pragma unroll
        for (int i = 0; i < 4; i++) co[nt][i] = 0.f;

    unsigned offQ = ((warp*16 + (lane & 15))*QKST + ((lane & 16) >> 2))*4;
    unsigned offP = ((warp*16 + (lane & 15))*PST2 + ((lane & 16) >> 2))*4;
    int rB = (lane & 7) + ((lane & 16) >> 1);
    int cB = (lane & 8) >> 1;
    unsigned offK[4], offV[4];
#pragma unroll
    for (int p = 0; p < 4; p++) {
        offK[p] = ((p*16 + rB)*QKST + cB)*4;
        offV[p] = ((p*16 + rB)*VST2 + cB)*4;
    }
    unsigned offV8 = ((64 + (lane & 7))*VST2 + cB)*4;

    const float scale = 0.11785113019775793f;  // 1/sqrt(72)

    for (int j0 = 0; j0 < S_TOK; j0 += AK2) {
        __syncthreads();
        // stage K (tf32 from rope) and V transposed [d][c] (tf32 here)
        for (int t = tid; t < AK2*18; t += 256) {
            int row = t/18, ch = t - row*18;
            float4 v = *(const float4*)&qkv[(size_t)(j0+row)*QKV_N + HID + h*HD + ch*4];
            *(float4*)&Ks[row*QKST + ch*4] = v;
        }
        for (int t = tid; t < AK2*18; t += 256) {
            int row = t/18, ch = t - row*18;
            float4 v = *(const float4*)&qkv[(size_t)(j0+row)*QKV_N + 2*HID + h*HD + ch*4];
            int d0 = ch*4;
            Vs[(d0+0)*VST2 + row] = to_tf32(v.x);
            Vs[(d0+1)*VST2 + row] = to_tf32(v.y);
            Vs[(d0+2)*VST2 + row] = to_tf32(v.z);
            Vs[(d0+3)*VST2 + row] = to_tf32(v.w);
        }
        if (tid < 64) segk[tid] = seg_of(j0 + tid, soffs);
        __syncthreads();

        // ---- S = Q K^T ----
        float sc[8][4];
#pragma unroll
        for (int nt = 0; nt < 8; nt++)
#pragma unroll
            for (int i = 0; i < 4; i++) sc[nt][i] = 0.f;
#pragma unroll
        for (int s = 0; s < HD; s += 8) {
            unsigned a[4], b[4][4];
            LDSM_X4(a, uQ + offQ + s*4);
#pragma unroll
            for (int p = 0; p < 4; p++) LDSM_X4(b[p], uK + offK[p] + s*4);
#pragma unroll
            for (int p = 0; p < 4; p++) {
                MMA_TF32(sc[2*p],   a, b[p][0], b[p][1]);
                MMA_TF32(sc[2*p+1], a, b[p][2], b[p][3]);
            }
        }
        // ---- bias + register softmax ----
        float mx1 = -1e30f, mx2 = -1e30f;
#pragma unroll
        for (int nt = 0; nt < 8; nt++) {
            int col = nt*8 + tg*2;
            int k0s = segk[col], k1s = segk[col+1];
            sc[nt][0] = sc[nt][0]*scale + (sq1 == k0s ? 1.f : 0.f);
            sc[nt][1] = sc[nt][1]*scale + (sq1 == k1s ? 1.f : 0.f);
            sc[nt][2] = sc[nt][2]*scale + (sq2 == k0s ? 1.f : 0.f);
            sc[nt][3] = sc[nt][3]*scale + (sq2 == k1s ? 1.f : 0.f);
            mx1 = fmaxf(mx1, fmaxf(sc[nt][0], sc[nt][1]));
            mx2 = fmaxf(mx2, fmaxf(sc[nt][2], sc[nt][3]));
        }
        mx1 = fmaxf(mx1, __shfl_xor_sync(0xffffffffu, mx1, 1, 4));
        mx1 = fmaxf(mx1, __shfl_xor_sync(0xffffffffu, mx1, 2, 4));
        mx2 = fmaxf(mx2, __shfl_xor_sync(0xffffffffu, mx2, 1, 4));
        mx2 = fmaxf(mx2, __shfl_xor_sync(0xffffffffu, mx2, 2, 4));
        float mn1 = fmaxf(m1, mx1), mn2 = fmaxf(m2, mx2);
        float f1 = __expf(m1 - mn1), f2 = __expf(m2 - mn2);
        m1 = mn1; m2 = mn2;
        float s1 = 0.f, s2 = 0.f;
#pragma unroll
        for (int nt = 0; nt < 8; nt++) {
            float p0 = to_tf32(__expf(sc[nt][0] - m1));
            float p1 = to_tf32(__expf(sc[nt][1] - m1));
            float p2 = to_tf32(__expf(sc[nt][2] - m2));
            float p3 = to_tf32(__expf(sc[nt][3] - m2));
            s1 += p0 + p1; s2 += p2 + p3;
            int col = nt*8 + tg*2;
            *(float2*)&Ps[r1*PST2 + col] = make_float2(p0, p1);
            *(float2*)&Ps[r2*PST2 + col] = make_float2(p2, p3);
        }
        s1 += __shfl_xor_sync(0xffffffffu, s1, 1, 4);
        s1 += __shfl_xor_sync(0xffffffffu, s1, 2, 4);
        s2 += __shfl_xor_sync(0xffffffffu, s2, 1, 4);
        s2 += __shfl_xor_sync(0xffffffffu, s2, 2, 4);
        l1 = l1*f1 + s1; l2 = l2*f2 + s2;
#pragma unroll
        for (int nt = 0; nt < 9; nt++) {
            co[nt][0] *= f1; co[nt][1] *= f1;
            co[nt][2] *= f2; co[nt][3] *= f2;
        }
        __syncthreads();
        // ---- O += P V ----
#pragma unroll
        for (int s = 0; s < AK2; s += 8) {
            unsigned a[4], b[4][4], b8[2];
            LDSM_X4(a, uP + offP + s*4);
#pragma unroll
            for (int p = 0; p < 4; p++) LDSM_X4(b[p], uV + offV[p] + s*4);
            LDSM_X2(b8, uV + offV8 + s*4);
#pragma unroll
            for (int p = 0; p < 4; p++) {
                MMA_TF32(co[2*p],   a, b[p][0], b[p][1]);
                MMA_TF32(co[2*p+1], a, b[p][2], b[p][3]);
            }
            MMA_TF32(co[8], a, b8[0], b8[1]);
        }
    }

    // epilogue: tf32-rounded (feeds Wo GEMM A operand)
    float i1 = 1.f/l1, i2 = 1.f/l2;
#pragma unroll
    for (int nt = 0; nt < 9; nt++) {
        int d0 = nt*8 + tg*2;
        *(float2*)&out[(size_t)(q0+r1)*HID + h*HD + d0] =
            make_float2(to_tf32(co[nt][0]*i1), to_tf32(co[nt][1]*i1));
        *(float2*)&out[(size_t)(q0+r2)*HID + h*HD + d0] =
            make_float2(to_tf32(co[nt][2]*i2), to_tf32(co[nt][3]*i2));
    }
}

// ---------------- launch ----------------
extern "C" void kernel_launch(void* const* d_in, const int* in_sizes, int n_in,
                              void* d_out, int out_size) {
    const float* x      = (const float*)d_in[0];
    const int*   offs   = (const int*)  d_in[1];
    const float* fc     = (const float*)d_in[2];
    const float* ln0_g  = (const float*)d_in[3];
    const float* ln0_b  = (const float*)d_in[4];
    const float* wqkv_w = (const float*)d_in[5];
    const float* wqkv_b = (const float*)d_in[6];
    const float* wo_w   = (const float*)d_in[7];
    const float* wo_b   = (const float*)d_in[8];
    const float* ln1_g  = (const float*)d_in[9];
    const float* ln1_b  = (const float*)d_in[10];
    const float* w1     = (const float*)d_in[11];
    const float* b1     = (const float*)d_in[12];
    const float* w2     = (const float*)d_in[13];
    const float* b2     = (const float*)d_in[14];
    float* out = (float*)d_out;

    float *h0, *qkv, *attn, *x2, *h1, *mlp;
    float *wqkvt, *wot, *w1t, *w2t;
    cudaGetSymbolAddress((void**)&h0,    g_h0);
    cudaGetSymbolAddress((void**)&qkv,   g_qkv);
    cudaGetSymbolAddress((void**)&attn,  g_attn);
    cudaGetSymbolAddress((void**)&x2,    g_x2);
    cudaGetSymbolAddress((void**)&h1,    g_h1);
    cudaGetSymbolAddress((void**)&mlp,   g_mlp);
    cudaGetSymbolAddress((void**)&wqkvt, g_wqkvt);
    cudaGetSymbolAddress((void**)&wot,   g_wot);
    cudaGetSymbolAddress((void**)&w1t,   g_w1t);
    cudaGetSymbolAddress((void**)&w2t,   g_w2t);

    const int GEMM_SMEM = STAGE_F*2*4;  // 73728 B
    cudaFuncSetAttribute(mma_gemm2, cudaFuncAttributeMaxDynamicSharedMemorySize, GEMM_SMEM);
    const int ATTN_SMEM = (AQ2*QKST + AK2*QKST + HD*VST2 + AQ2*PST2)*4 + (64+8)*4;
    cudaFuncSetAttribute(attn2_kernel, cudaFuncAttributeMaxDynamicSharedMemorySize, ATTN_SMEM);

    // 0. transpose weights -> [N][K] (tf32-rounded). CEIL-DIV grids (MLP_DIM % 32 != 0)
    transpose_kernel<<<dim3((QKV_N+31)/32, (HID+31)/32), dim3(32,8)>>>(wqkv_w, wqkvt, HID, QKV_N);
    transpose_kernel<<<dim3((HID+31)/32, (HID+31)/32),   dim3(32,8)>>>(wo_w,   wot,   HID, HID);
    transpose_kernel<<<dim3((MLP_DIM+31)/32, (HID+31)/32), dim3(32,8)>>>(w1, w1t, HID, MLP_DIM);
    transpose_kernel<<<dim3((HID+31)/32, (MLP_DIM+31)/32), dim3(32,8)>>>(w2, w2t, MLP_DIM, HID);

    // 1. LN0 (tf32 out)
    ln_kernel<<<S_TOK, 256>>>(x, ln0_g, ln0_b, h0);
    // 2. QKV
    mma_gemm2<<<dim3(QKV_N/GBN, S_TOK/GBM), 256, GEMM_SMEM>>>(
        h0, wqkvt, wqkv_b, nullptr, qkv, S_TOK, QKV_N, HID, (HID+GBK-1)/GBK, 0);
    // 3. RoPE (tf32 out on q,k)
    {
        int total = 2 * S_TOK * NH * (HD/2);
        rope_kernel<<<(total + 255)/256, 256>>>(qkv, fc);
    }
    // 4. attention
    attn2_kernel<<<dim3(S_TOK/AQ2, NH), 256, ATTN_SMEM>>>(qkv, offs, attn);
    // 5. x2 = x + attn @ wo + b
    mma_gemm2<<<dim3(HID/GBN, S_TOK/GBM), 256, GEMM_SMEM>>>(
        attn, wot, wo_b, x, x2, S_TOK, HID, HID, (HID+GBK-1)/GBK, 1);
    // 6. LN1 (tf32 out)
    ln_kernel<<<S_TOK, 256>>>(x2, ln1_g, ln1_b, h1);
    // 7. mlp = gelu(h1 @ w1 + b1)  (tf32 out)
    mma_gemm2<<<dim3((MLP_DIM+GBN-1)/GBN, S_TOK/GBM), 256, GEMM_SMEM>>>(
        h1, w1t, b1, nullptr, mlp, S_TOK, MLP_DIM, HID, (HID+GBK-1)/GBK, 2);
    // 8. out = x2 + mlp @ w2 + b2
    mma_gemm2<<<dim3(HID/GBN, S_TOK/GBM), 256, GEMM_SMEM>>>(
        mlp, w2t, b2, x2, out, S_TOK, HID, MLP_DIM, (MLP_DIM+GBK-1)/GBK, 1);
}

// round 7
// speedup vs baseline: 2.7149x; 1.0043x over previous
#include <cuda_runtime.h>
#include <cuda_bf16.h>
#include <math.h>

// Problem constants
#define S_TOK 3072
#define HID 1152
#define NH 16
#define HD 72
#define MLP_DIM 4304
#define QKV_N (3*HID)   // 3456
#define EPS 1e-5f

// ---------------- scratch (allocation-free: __device__ globals) ----------------
__device__ float g_h0[S_TOK*HID];
__device__ float g_qkv[S_TOK*QKV_N];
__device__ float g_attn[S_TOK*HID];
__device__ float g_x2[S_TOK*HID];
__device__ float g_h1[S_TOK*HID];
__device__ float g_mlp[S_TOK*MLP_DIM];
// transposed weights [N][K] (tf32-rounded)
__device__ float g_wqkvt[QKV_N*HID];
__device__ float g_wot[HID*HID];
__device__ float g_w1t[MLP_DIM*HID];
__device__ float g_w2t[HID*MLP_DIM];

// ---------------- PTX helpers ----------------
#define MMA_TF32(C, A, B0, B1)                                            \
    asm volatile("mma.sync.aligned.m16n8k8.row.col.f32.tf32.tf32.f32 "    \
                 "{%0,%1,%2,%3}, {%4,%5,%6,%7}, {%8,%9}, {%0,%1,%2,%3};\n"\
                 : "+f"((C)[0]), "+f"((C)[1]), "+f"((C)[2]), "+f"((C)[3]) \
                 : "r"((A)[0]), "r"((A)[1]), "r"((A)[2]), "r"((A)[3]),    \
                   "r"(B0), "r"(B1))

#define LDSM_X4(R, a)                                                          \
    asm volatile("ldmatrix.sync.aligned.m8n8.x4.shared.b16 {%0,%1,%2,%3}, [%4];" \
                 : "=r"((R)[0]), "=r"((R)[1]), "=r"((R)[2]), "=r"((R)[3])      \
                 : "r"(a))
#define LDSM_X2(R, a)                                                          \
    asm volatile("ldmatrix.sync.aligned.m8n8.x2.shared.b16 {%0,%1}, [%2];"     \
                 : "=r"((R)[0]), "=r"((R)[1]) : "r"(a))

__device__ __forceinline__ void cp_async16(unsigned dst, const void* src, bool valid) {
    int sz = valid ? 16 : 0;
    asm volatile("cp.async.cg.shared.global [%0], [%1], 16, %2;"
                 :: "r"(dst), "l"(src), "r"(sz));
}
#define CP_COMMIT asm volatile("cp.async.commit_group;")
#define CP_WAIT1  asm volatile("cp.async.wait_group 1;")

__device__ __forceinline__ float gelu_fast(float v) {
    float u = 0.7978845608028654f * (v + 0.044715f * v * v * v);
    // 0.5*v*(1+tanh(u)) == v / (1 + exp(-2u)); safe at both saturations
    return v / (1.0f + __expf(-2.0f * u));
}
__device__ __forceinline__ float to_tf32(float x) {
    unsigned r;
    asm("cvt.rna.tf32.f32 %0, %1;" : "=r"(r) : "f"(x));
    return __uint_as_float(r);
}

// ---------------- LayerNorm (emits tf32-rounded output: feeds GEMM A) ------
__global__ void ln_kernel(const float* __restrict__ x, const float* __restrict__ g,
                          const float* __restrict__ b, float* __restrict__ y) {
    __shared__ float row[HID];
    __shared__ float red_s[256], red_ss[256];
    int r = blockIdx.x;
    int tid = threadIdx.x;
    float s = 0.f, ss = 0.f;
    for (int i = tid; i < HID; i += 256) {
        float v = x[(size_t)r*HID + i];
        row[i] = v;
        s += v; ss += v*v;
    }
    red_s[tid] = s; red_ss[tid] = ss;
    __syncthreads();
    for (int o = 128; o > 0; o >>= 1) {
        if (tid < o) { red_s[tid] += red_s[tid+o]; red_ss[tid] += red_ss[tid+o]; }
        __syncthreads();
    }
    float mu = red_s[0] * (1.0f/HID);
    float var = red_ss[0] * (1.0f/HID) - mu*mu;
    float rstd = rsqrtf(var + EPS);
    for (int i = tid; i < HID; i += 256) {
        y[(size_t)r*HID + i] = to_tf32((row[i] - mu) * rstd * g[i] + b[i]);
    }
}

// ---------------- weight transpose: [K][N] -> [N][K], tf32-rounded ----------
__global__ void transpose_kernel(const float* __restrict__ in, float* __restrict__ out,
                                 int K, int N) {
    __shared__ float t[32][33];
    int kb = blockIdx.y*32, nb = blockIdx.x*32;
    int x = threadIdx.x, y = threadIdx.y;   // 32 x 8
#pragma unroll
    for (int i = 0; i < 32; i += 8) {
        int k = kb + y + i, n = nb + x;
        t[y+i][x] = (k < K && n < N) ? in[(size_t)k*N + n] : 0.f;
    }
    __syncthreads();
#pragma unroll
    for (int i = 0; i < 32; i += 8) {
        int n = nb + y + i, k = kb + x;
        if (n < N && k < K) out[(size_t)n*K + k] = to_tf32(t[x][y+i]);
    }
}

// ---------------- tf32 GEMM: ldmatrix + cp.async 3-stage pipeline ----------------
// C[M,N] = A[M,K] @ Bt[N,K]^T + bias (+residual/gelu). A,Bt pre-rounded to tf32.
#define GBM 128
#define GBN 128
#define GBK 32
#define GST 36                 // smem row stride (floats)
#define STG_F (GBM*GST)        // 4608 floats per As / Bs tile
#define STAGE_F (2*STG_F)      // 9216 per stage
#define NSTAGE 3

__global__ void __launch_bounds__(256, 2)
mma_gemm2(const float* __restrict__ A, const float* __restrict__ Bt,
          const float* __restrict__ bias, const float* __restrict__ residual,
          float* __restrict__ C, int M, int N, int K, int NIT, int mode) {
    extern __shared__ float smg[];
    unsigned sbase = (unsigned)__cvta_generic_to_shared(smg);
    int tid = threadIdx.x, warp = tid >> 5, lane = tid & 31;
    int g = lane >> 2, tg = lane & 3;
    int wy = warp >> 1, wx = warp & 1;
    int m0 = blockIdx.y*GBM, n0 = blockIdx.x*GBN;

    float c[2][8][4];
#pragma unroll
    for (int mt = 0; mt < 2; mt++)
#pragma unroll
        for (int nt = 0; nt < 8; nt++)
#pragma unroll
            for (int i = 0; i < 4; i++) c[mt][nt][i] = 0.f;

    auto stage = [&](int it, int buf) {
        int k0 = it*GBK;
        unsigned sA = sbase + buf*STAGE_F*4;
        unsigned sB = sA + STG_F*4;
#pragma unroll
        for (int i = 0; i < 4; i++) {
            int t = tid + i*256;
            int row = t >> 3, ch = t & 7;
            int k = k0 + ch*4;
            bool v = (k < K);
            cp_async16(sA + (row*GST + ch*4)*4,
                       A + (size_t)(m0+row)*K + (v ? k : 0), v);
        }
#pragma unroll
        for (int i = 0; i < 4; i++) {
            int t = tid + i*256;
            int row = t >> 3, ch = t & 7;
            int k = k0 + ch*4;
            int n = n0 + row;
            bool v = (k < K) && (n < N);
            cp_async16(sB + (row*GST + ch*4)*4,
                       Bt + (size_t)(v ? n : 0)*K + (v ? k : 0), v);
        }
    };

    stage(0, 0); CP_COMMIT;
    if (NIT > 1) stage(1, 1);
    CP_COMMIT;

    unsigned offA[2], offB[4];
    {
        int rA = lane & 15, cA = (lane & 16) ? 4 : 0;
#pragma unroll
        for (int mt = 0; mt < 2; mt++)
            offA[mt] = ((wy*32 + mt*16 + rA)*GST + cA)*4;
        int rB = (lane & 7) + ((lane & 16) >> 1);
        int cB = (lane & 8) ? 4 : 0;
#pragma unroll
        for (int p = 0; p < 4; p++)
            offB[p] = ((wx*64 + p*16 + rB)*GST + cB)*4;
    }

    int buf = 0;
    for (int it = 0; it < NIT; it++) {
        CP_WAIT1;            // group `it` complete
        __syncthreads();     // all warps done with compute(it-1); buf (it+2)%3 free
        int nb = buf + 2; if (nb >= NSTAGE) nb -= NSTAGE;
        if (it + 2 < NIT) stage(it+2, nb);
        CP_COMMIT;
        unsigned sA = sbase + buf*STAGE_F*4;
        unsigned sB = sA + STG_F*4;
#pragma unroll
        for (int s = 0; s < GBK; s += 8) {
            unsigned a[2][4], b[4][4];
            LDSM_X4(a[0], sA + offA[0] + s*4);
            LDSM_X4(a[1], sA + offA[1] + s*4);
#pragma unroll
            for (int p = 0; p < 4; p++) LDSM_X4(b[p], sB + offB[p] + s*4);
#pragma unroll
            for (int mt = 0; mt < 2; mt++)
#pragma unroll
                for (int p = 0; p < 4; p++) {
                    MMA_TF32(c[mt][2*p],   a[mt], b[p][0], b[p][1]);
                    MMA_TF32(c[mt][2*p+1], a[mt], b[p][2], b[p][3]);
                }
        }
        if (++buf == NSTAGE) buf = 0;
    }

    // epilogue
#pragma unroll
    for (int mt = 0; mt < 2; mt++) {
        int row0 = m0 + wy*32 + mt*16 + g;
#pragma unroll
        for (int nt = 0; nt < 8; nt++) {
            int col = n0 + wx*64 + nt*8 + tg*2;
            if (col >= N) continue;
#pragma unroll
            for (int hf = 0; hf < 2; hf++) {
                int r = row0 + hf*8;
                float v0 = c[mt][nt][hf*2+0] + bias[col];
                float v1 = c[mt][nt][hf*2+1] + bias[col+1];
                if (mode == 1) {
                    v0 += residual[(size_t)r*N + col];
                    v1 += residual[(size_t)r*N + col + 1];
                } else if (mode == 2) {
                    v0 = to_tf32(gelu_fast(v0));   // feeds next GEMM A
                    v1 = to_tf32(gelu_fast(v1));
                }
                *(float2*)&C[(size_t)r*N + col] = make_float2(v0, v1);
            }
        }
    }
}

// ---------------- attention: AQ=128, fused RoPE, register softmax, ldmatrix ----
#define AQ2 128
#define AK2 64
#define QKST 76    // Qs/Ks row stride
#define VST2 68    // Vs [d][tok] stride
#define PST2 68    // Ps [q][tok] stride

__device__ __forceinline__ int seg_of(int t, const int* offs) {
    int s = 0;
#pragma unroll
    for (int i = 1; i <= 6; i++) if (offs[i] <= t) s = i;
    return s;
}

__global__ void __launch_bounds__(256, 1)
attn2_kernel(const float* __restrict__ qkv, const float* __restrict__ fc,
             const int* __restrict__ offs, float* __restrict__ out) {
    extern __shared__ float sm[];
    float* Qs = sm;                          // 128*76
    float* Ks = Qs + AQ2*QKST;               // 64*76
    float* Vs = Ks + AK2*QKST;               // 72*68
    float* Ps = Vs + HD*VST2;                // 128*68
    int* segk  = (int*)(Ps + AQ2*PST2);      // 64
    int* soffs = segk + 64;                  // 8

    unsigned sbase = (unsigned)__cvta_generic_to_shared(sm);
    unsigned uQ = sbase;
    unsigned uK = sbase + AQ2*QKST*4;
    unsigned uV = uK + AK2*QKST*4;
    unsigned uP = uV + HD*VST2*4;

    int tid = threadIdx.x, warp = tid >> 5, lane = tid & 31;
    int g = lane >> 2, tg = lane & 3;
    int h = blockIdx.y, q0 = blockIdx.x*AQ2;

    if (tid < 7) soffs[tid] = offs[tid];

    // stage Q with fused RoPE + tf32 rounding
    for (int t = tid; t < AQ2*18; t += 256) {
        int row = t/18, ch = t - row*18;
        int tok = q0 + row, d0 = ch*4;
        float4 v = *(const float4*)&qkv[(size_t)tok*QKV_N + h*HD + d0];
        float2 cs0 = *(const float2*)&fc[(size_t)tok*HD + d0];
        float2 cs1 = *(const float2*)&fc[(size_t)tok*HD + d0 + 2];
        float4 o;
        o.x = to_tf32(v.x*cs0.x - v.y*cs0.y);
        o.y = to_tf32(v.x*cs0.y + v.y*cs0.x);
        o.z = to_tf32(v.z*cs1.x - v.w*cs1.y);
        o.w = to_tf32(v.z*cs1.y + v.w*cs1.x);
        *(float4*)&Qs[row*QKST + d0] = o;
    }
    __syncthreads();

    int r1 = warp*16 + g, r2 = r1 + 8;
    int sq1 = seg_of(q0 + r1, soffs);
    int sq2 = seg_of(q0 + r2, soffs);

    float m1 = -1e30f, m2 = -1e30f, l1 = 0.f, l2 = 0.f;
    float co[9][4];
#pragma unroll
    for (int nt = 0; nt < 9; nt++)
#pragma unroll
        for (int i = 0; i < 4; i++) co[nt][i] = 0.f;

    unsigned offQ = ((warp*16 + (lane & 15))*QKST + ((lane & 16) >> 2))*4;
    unsigned offP = ((warp*16 + (lane & 15))*PST2 + ((lane & 16) >> 2))*4;
    int rB = (lane & 7) + ((lane & 16) >> 1);
    int cB = (lane & 8) >> 1;
    unsigned offK[4], offV[4];
#pragma unroll
    for (int p = 0; p < 4; p++) {
        offK[p] = ((p*16 + rB)*QKST + cB)*4;
        offV[p] = ((p*16 + rB)*VST2 + cB)*4;
    }
    unsigned offV8 = ((64 + (lane & 7))*VST2 + cB)*4;

    const float scale = 0.11785113019775793f;  // 1/sqrt(72)

    for (int j0 = 0; j0 < S_TOK; j0 += AK2) {
        __syncthreads();
        // stage K with fused RoPE + tf32; V transposed [d][c] with tf32
        for (int t = tid; t < AK2*18; t += 256) {
            int row = t/18, ch = t - row*18;
            int tok = j0 + row, d0 = ch*4;
            float4 v = *(const float4*)&qkv[(size_t)tok*QKV_N + HID + h*HD + d0];
            float2 cs0 = *(const float2*)&fc[(size_t)tok*HD + d0];
            float2 cs1 = *(const float2*)&fc[(size_t)tok*HD + d0 + 2];
            float4 o;
            o.x = to_tf32(v.x*cs0.x - v.y*cs0.y);
            o.y = to_tf32(v.x*cs0.y + v.y*cs0.x);
            o.z = to_tf32(v.z*cs1.x - v.w*cs1.y);
            o.w = to_tf32(v.z*cs1.y + v.w*cs1.x);
            *(float4*)&Ks[row*QKST + d0] = o;
        }
        for (int t = tid; t < AK2*18; t += 256) {
            int row = t/18, ch = t - row*18;
            float4 v = *(const float4*)&qkv[(size_t)(j0+row)*QKV_N + 2*HID + h*HD + ch*4];
            int d0 = ch*4;
            Vs[(d0+0)*VST2 + row] = to_tf32(v.x);
            Vs[(d0+1)*VST2 + row] = to_tf32(v.y);
            Vs[(d0+2)*VST2 + row] = to_tf32(v.z);
            Vs[(d0+3)*VST2 + row] = to_tf32(v.w);
        }
        if (tid < 64) segk[tid] = seg_of(j0 + tid, soffs);
        __syncthreads();

        // ---- S = Q K^T ----
        float sc[8][4];
#pragma unroll
        for (int nt = 0; nt < 8; nt++)
#pragma unroll
            for (int i = 0; i < 4; i++) sc[nt][i] = 0.f;
#pragma unroll
        for (int s = 0; s < HD; s += 8) {
            unsigned a[4], b[4][4];
            LDSM_X4(a, uQ + offQ + s*4);
#pragma unroll
            for (int p = 0; p < 4; p++) LDSM_X4(b[p], uK + offK[p] + s*4);
#pragma unroll
            for (int p = 0; p < 4; p++) {
                MMA_TF32(sc[2*p],   a, b[p][0], b[p][1]);
                MMA_TF32(sc[2*p+1], a, b[p][2], b[p][3]);
            }
        }
        // ---- bias + register softmax ----
        float mx1 = -1e30f, mx2 = -1e30f;
#pragma unroll
        for (int nt = 0; nt < 8; nt++) {
            int col = nt*8 + tg*2;
            int k0s = segk[col], k1s = segk[col+1];
            sc[nt][0] = sc[nt][0]*scale + (sq1 == k0s ? 1.f : 0.f);
            sc[nt][1] = sc[nt][1]*scale + (sq1 == k1s ? 1.f : 0.f);
            sc[nt][2] = sc[nt][2]*scale + (sq2 == k0s ? 1.f : 0.f);
            sc[nt][3] = sc[nt][3]*scale + (sq2 == k1s ? 1.f : 0.f);
            mx1 = fmaxf(mx1, fmaxf(sc[nt][0], sc[nt][1]));
            mx2 = fmaxf(mx2, fmaxf(sc[nt][2], sc[nt][3]));
        }
        mx1 = fmaxf(mx1, __shfl_xor_sync(0xffffffffu, mx1, 1, 4));
        mx1 = fmaxf(mx1, __shfl_xor_sync(0xffffffffu, mx1, 2, 4));
        mx2 = fmaxf(mx2, __shfl_xor_sync(0xffffffffu, mx2, 1, 4));
        mx2 = fmaxf(mx2, __shfl_xor_sync(0xffffffffu, mx2, 2, 4));
        float mn1 = fmaxf(m1, mx1), mn2 = fmaxf(m2, mx2);
        float f1 = __expf(m1 - mn1), f2 = __expf(m2 - mn2);
        m1 = mn1; m2 = mn2;
        float s1 = 0.f, s2 = 0.f;
#pragma unroll
        for (int nt = 0; nt < 8; nt++) {
            float p0 = to_tf32(__expf(sc[nt][0] - m1));
            float p1 = to_tf32(__expf(sc[nt][1] - m1));
            float p2 = to_tf32(__expf(sc[nt][2] - m2));
            float p3 = to_tf32(__expf(sc[nt][3] - m2));
            s1 += p0 + p1; s2 += p2 + p3;
            int col = nt*8 + tg*2;
            *(float2*)&Ps[r1*PST2 + col] = make_float2(p0, p1);
            *(float2*)&Ps[r2*PST2 + col] = make_float2(p2, p3);
        }
        s1 += __shfl_xor_sync(0xffffffffu, s1, 1, 4);
        s1 += __shfl_xor_sync(0xffffffffu, s1, 2, 4);
        s2 += __shfl_xor_sync(0xffffffffu, s2, 1, 4);
        s2 += __shfl_xor_sync(0xffffffffu, s2, 2, 4);
        l1 = l1*f1 + s1; l2 = l2*f2 + s2;
#pragma unroll
        for (int nt = 0; nt < 9; nt++) {
            co[nt][0] *= f1; co[nt][1] *= f1;
            co[nt][2] *= f2; co[nt][3] *= f2;
        }
        __syncthreads();
        // ---- O += P V ----
#pragma unroll
        for (int s = 0; s < AK2; s += 8) {
            unsigned a[4], b[4][4], b8[2];
            LDSM_X4(a, uP + offP + s*4);
#pragma unroll
            for (int p = 0; p < 4; p++) LDSM_X4(b[p], uV + offV[p] + s*4);
            LDSM_X2(b8, uV + offV8 + s*4);
#pragma unroll
            for (int p = 0; p < 4; p++) {
                MMA_TF32(co[2*p],   a, b[p][0], b[p][1]);
                MMA_TF32(co[2*p+1], a, b[p][2], b[p][3]);
            }
            MMA_TF32(co[8], a, b8[0], b8[1]);
        }
    }

    // epilogue: tf32-rounded (feeds Wo GEMM A operand)
    float i1 = 1.f/l1, i2 = 1.f/l2;
#pragma unroll
    for (int nt = 0; nt < 9; nt++) {
        int d0 = nt*8 + tg*2;
        *(float2*)&out[(size_t)(q0+r1)*HID + h*HD + d0] =
            make_float2(to_tf32(co[nt][0]*i1), to_tf32(co[nt][1]*i1));
        *(float2*)&out[(size_t)(q0+r2)*HID + h*HD + d0] =
            make_float2(to_tf32(co[nt][2]*i2), to_tf32(co[nt][3]*i2));
    }
}

// ---------------- launch ----------------
extern "C" void kernel_launch(void* const* d_in, const int* in_sizes, int n_in,
                              void* d_out, int out_size) {
    const float* x      = (const float*)d_in[0];
    const int*   offs   = (const int*)  d_in[1];
    const float* fc     = (const float*)d_in[2];
    const float* ln0_g  = (const float*)d_in[3];
    const float* ln0_b  = (const float*)d_in[4];
    const float* wqkv_w = (const float*)d_in[5];
    const float* wqkv_b = (const float*)d_in[6];
    const float* wo_w   = (const float*)d_in[7];
    const float* wo_b   = (const float*)d_in[8];
    const float* ln1_g  = (const float*)d_in[9];
    const float* ln1_b  = (const float*)d_in[10];
    const float* w1     = (const float*)d_in[11];
    const float* b1     = (const float*)d_in[12];
    const float* w2     = (const float*)d_in[13];
    const float* b2     = (const float*)d_in[14];
    float* out = (float*)d_out;

    float *h0, *qkv, *attn, *x2, *h1, *mlp;
    float *wqkvt, *wot, *w1t, *w2t;
    cudaGetSymbolAddress((void**)&h0,    g_h0);
    cudaGetSymbolAddress((void**)&qkv,   g_qkv);
    cudaGetSymbolAddress((void**)&attn,  g_attn);
    cudaGetSymbolAddress((void**)&x2,    g_x2);
    cudaGetSymbolAddress((void**)&h1,    g_h1);
    cudaGetSymbolAddress((void**)&mlp,   g_mlp);
    cudaGetSymbolAddress((void**)&wqkvt, g_wqkvt);
    cudaGetSymbolAddress((void**)&wot,   g_wot);
    cudaGetSymbolAddress((void**)&w1t,   g_w1t);
    cudaGetSymbolAddress((void**)&w2t,   g_w2t);

    const int GEMM_SMEM = NSTAGE*STAGE_F*4;  // 110592 B
    cudaFuncSetAttribute(mma_gemm2, cudaFuncAttributeMaxDynamicSharedMemorySize, GEMM_SMEM);
    const int ATTN_SMEM = (AQ2*QKST + AK2*QKST + HD*VST2 + AQ2*PST2)*4 + (64+8)*4;
    cudaFuncSetAttribute(attn2_kernel, cudaFuncAttributeMaxDynamicSharedMemorySize, ATTN_SMEM);

    // 0. transpose weights -> [N][K] (tf32-rounded), CEIL-DIV grids
    transpose_kernel<<<dim3((QKV_N+31)/32, (HID+31)/32), dim3(32,8)>>>(wqkv_w, wqkvt, HID, QKV_N);
    transpose_kernel<<<dim3((HID+31)/32, (HID+31)/32),   dim3(32,8)>>>(wo_w,   wot,   HID, HID);
    transpose_kernel<<<dim3((MLP_DIM+31)/32, (HID+31)/32), dim3(32,8)>>>(w1, w1t, HID, MLP_DIM);
    transpose_kernel<<<dim3((HID+31)/32, (MLP_DIM+31)/32), dim3(32,8)>>>(w2, w2t, MLP_DIM, HID);

    // 1. LN0 (tf32 out)
    ln_kernel<<<S_TOK, 256>>>(x, ln0_g, ln0_b, h0);
    // 2. QKV (raw fp32 out; rope+tf32 applied at attention staging)
    mma_gemm2<<<dim3(QKV_N/GBN, S_TOK/GBM), 256, GEMM_SMEM>>>(
        h0, wqkvt, wqkv_b, nullptr, qkv, S_TOK, QKV_N, HID, (HID+GBK-1)/GBK, 0);
    // 3. attention (fused rope)
    attn2_kernel<<<dim3(S_TOK/AQ2, NH), 256, ATTN_SMEM>>>(qkv, fc, offs, attn);
    // 4. x2 = x + attn @ wo + b
    mma_gemm2<<<dim3(HID/GBN, S_TOK/GBM), 256, GEMM_SMEM>>>(
        attn, wot, wo_b, x, x2, S_TOK, HID, HID, (HID+GBK-1)/GBK, 1);
    // 5. LN1 (tf32 out)
    ln_kernel<<<S_TOK, 256>>>(x2, ln1_g, ln1_b, h1);
    // 6. mlp = gelu(h1 @ w1 + b1)  (tf32 out)
    mma_gemm2<<<dim3((MLP_DIM+GBN-1)/GBN, S_TOK/GBM), 256, GEMM_SMEM>>>(
        h1, w1t, b1, nullptr, mlp, S_TOK, MLP_DIM, HID, (HID+GBK-1)/GBK, 2);
    // 7. out = x2 + mlp @ w2 + b2
    mma_gemm2<<<dim3(HID/GBN, S_TOK/GBM), 256, GEMM_SMEM>>>(
        mlp, w2t, b2, x2, out, S_TOK, HID, MLP_DIM, (MLP_DIM+GBK-1)/GBK, 1);
}

// round 10
// speedup vs baseline: 4.9796x; 1.8342x over previous
#include <cuda_runtime.h>
#include <cuda_bf16.h>
#include <cuda_fp16.h>
#include <stdint.h>
#include <math.h>

// Problem constants
#define S_TOK 3072
#define HID 1152
#define NH 16
#define HD 72
#define MLP_DIM 4304
#define MLP_P2 4352           // MLP_DIM padded to multiple of 64 (zeros in pad)
#define QKV_N (3*HID)         // 3456
#define EPS 1e-5f

// ---------------- scratch (allocation-free: __device__ globals, zero-init) ----
// fp32 intermediates
__device__ float g_qkv[S_TOK*QKV_N];
__device__ float g_x2[S_TOK*HID];
// fp16 operands (ushort so zero-init is unambiguous; cast to __half*)
__device__ unsigned short g_h0h[S_TOK*HID];
__device__ unsigned short g_attnh[S_TOK*HID];
__device__ unsigned short g_h1h[S_TOK*HID];
__device__ unsigned short g_mlph[S_TOK*MLP_P2];     // cols 4304..4351 stay zero
__device__ unsigned short g_wqkvth[QKV_N*HID];
__device__ unsigned short g_woth[HID*HID];
__device__ unsigned short g_w1th[MLP_DIM*HID];
__device__ unsigned short g_w2th[HID*MLP_P2];       // k 4304..4351 stay zero

// ---------------- PTX helpers ----------------
__device__ __forceinline__ uint32_t smem_u32(const void* p) {
    uint32_t a;
    asm("{ .reg .u64 t; cvta.to.shared.u64 t, %1; cvt.u32.u64 %0, t; }"
        : "=r"(a) : "l"(p));
    return a;
}

#define MMA_F16(C, A, B0, B1)                                               \
    asm volatile("mma.sync.aligned.m16n8k16.row.col.f32.f16.f16.f32 "       \
                 "{%0,%1,%2,%3}, {%4,%5,%6,%7}, {%8,%9}, {%0,%1,%2,%3};\n"  \
                 : "+f"((C)[0]), "+f"((C)[1]), "+f"((C)[2]), "+f"((C)[3])   \
                 : "r"((A)[0]), "r"((A)[1]), "r"((A)[2]), "r"((A)[3]),      \
                   "r"(B0), "r"(B1))

#define LDSM_X4(R, a)                                                          \
    asm volatile("ldmatrix.sync.aligned.m8n8.x4.shared.b16 {%0,%1,%2,%3}, [%4];" \
                 : "=r"((R)[0]), "=r"((R)[1]), "=r"((R)[2]), "=r"((R)[3])      \
                 : "r"(a))
#define LDSM_X2(R, a)                                                          \
    asm volatile("ldmatrix.sync.aligned.m8n8.x2.shared.b16 {%0,%1}, [%2];"     \
                 : "=r"((R)[0]), "=r"((R)[1]) : "r"(a))

__device__ __forceinline__ void cp_async16(unsigned dst, const void* src, bool valid) {
    int sz = valid ? 16 : 0;
    asm volatile("cp.async.cg.shared.global [%0], [%1], 16, %2;"
                 :: "r"(dst), "l"(src), "r"(sz));
}
#define CP_COMMIT asm volatile("cp.async.commit_group;")
#define CP_WAIT1  asm volatile("cp.async.wait_group 1;")

__device__ __forceinline__ float gelu_fast(float v) {
    float u = 0.7978845608028654f * (v + 0.044715f * v * v * v);
    return v / (1.0f + __expf(-2.0f * u));
}

// ---------------- LayerNorm (emits fp16 output: feeds GEMM A) --------------
__global__ void ln_kernel(const float* __restrict__ x, const float* __restrict__ g,
                          const float* __restrict__ b, __half* __restrict__ y) {
    __shared__ float row[HID];
    __shared__ float red_s[256], red_ss[256];
    int r = blockIdx.x;
    int tid = threadIdx.x;
    float s = 0.f, ss = 0.f;
    for (int i = tid; i < HID; i += 256) {
        float v = x[(size_t)r*HID + i];
        row[i] = v;
        s += v; ss += v*v;
    }
    red_s[tid] = s; red_ss[tid] = ss;
    __syncthreads();
    for (int o = 128; o > 0; o >>= 1) {
        if (tid < o) { red_s[tid] += red_s[tid+o]; red_ss[tid] += red_ss[tid+o]; }
        __syncthreads();
    }
    float mu = red_s[0] * (1.0f/HID);
    float var = red_ss[0] * (1.0f/HID) - mu*mu;
    float rstd = rsqrtf(var + EPS);
    for (int i = tid; i < HID; i += 256) {
        y[(size_t)r*HID + i] = __float2half_rn((row[i] - mu) * rstd * g[i] + b[i]);
    }
}

// ---------------- weight transpose: [K][N] fp32 -> [N][K(out_ld)] fp16 ------
__global__ void transpose_kernel(const float* __restrict__ in, __half* __restrict__ out,
                                 int K, int N, int out_ld) {
    __shared__ float t[32][33];
    int kb = blockIdx.y*32, nb = blockIdx.x*32;
    int x = threadIdx.x, y = threadIdx.y;   // 32 x 8
#pragma unroll
    for (int i = 0; i < 32; i += 8) {
        int k = kb + y + i, n = nb + x;
        t[y+i][x] = (k < K && n < N) ? in[(size_t)k*N + n] : 0.f;
    }
    __syncthreads();
#pragma unroll
    for (int i = 0; i < 32; i += 8) {
        int n = nb + y + i, k = kb + x;
        if (n < N && k < K) out[(size_t)n*out_ld + k] = __float2half_rn(t[x][y+i]);
    }
}

// ---------------- fp16 GEMM: ldmatrix + cp.async 3-stage pipeline -----------
// C[M,N] = A[M,K] @ Bt[N,K]^T + bias (+residual / gelu). A,Bt are __half.
// mode 0: bias, fp32 out; 1: bias+residual, fp32 out; 2: bias+gelu, fp16 out
#define GBK 64
#define TILE_B (128*128)             // bytes: 128 rows * 64 halfs
#define STAGE_B (2*TILE_B)           // 32768
#define NSTAGE 3
#define GEMM_SMEM (NSTAGE*STAGE_B)   // 98304

__global__ void __launch_bounds__(256, 2)
hgemm(const __half* __restrict__ A, int ldA,
      const __half* __restrict__ Bt, int ldB,
      const float* __restrict__ bias, const float* __restrict__ residual,
      void* __restrict__ Cv, int ldC, int N, int NIT, int mode) {
    extern __shared__ char smg[];
    unsigned sbase = smem_u32(smg);
    int tid = threadIdx.x, warp = tid >> 5, lane = tid & 31;
    int g = lane >> 2, tg = lane & 3;
    int wy = warp >> 1, wx = warp & 1;
    int m0 = blockIdx.y*128, n0 = blockIdx.x*128;

    float c[2][8][4];
#pragma unroll
    for (int mt = 0; mt < 2; mt++)
#pragma unroll
        for (int nt = 0; nt < 8; nt++)
#pragma unroll
            for (int i = 0; i < 4; i++) c[mt][nt][i] = 0.f;

    auto stage = [&](int it, int buf) {
        int k0 = it*GBK;
        unsigned sA = sbase + buf*STAGE_B;
        unsigned sB = sA + TILE_B;
#pragma unroll
        for (int i = 0; i < 4; i++) {
            int t = tid + i*256;
            int row = t >> 3, ch = t & 7;
            unsigned off = (unsigned)(row*128) + ((unsigned)(ch ^ (row & 7)) << 4);
            cp_async16(sA + off, A + (size_t)(m0+row)*ldA + k0 + ch*8, true);
            int n = n0 + row;
            bool v = (n < N);
            cp_async16(sB + off, Bt + (size_t)(v ? n : 0)*ldB + k0 + ch*8, v);
        }
    };

    stage(0, 0); CP_COMMIT;
    if (NIT > 1) stage(1, 1);
    CP_COMMIT;

    // ldmatrix lane offsets (XOR-swizzled 128B rows)
    unsigned hi = (unsigned)(lane >> 4);           // 0/1 -> k-half within k16
    unsigned aoff[2], amask[2], boff[4], bmask[4];
#pragma unroll
    for (int mt = 0; mt < 2; mt++) {
        int r = wy*32 + mt*16 + (lane & 15);
        aoff[mt] = (unsigned)(r*128); amask[mt] = (unsigned)(r & 7);
    }
#pragma unroll
    for (int p = 0; p < 4; p++) {
        int r = wx*64 + p*16 + (lane & 15);
        boff[p] = (unsigned)(r*128); bmask[p] = (unsigned)(r & 7);
    }

    for (int it = 0; it < NIT; it++) {
        CP_WAIT1;            // group `it` complete
        __syncthreads();     // compute(it-1) done everywhere; buf (it+2)%3 free
        if (it + 2 < NIT) stage(it+2, (it+2)%NSTAGE);
        CP_COMMIT;
        unsigned sA = sbase + (it%NSTAGE)*STAGE_B;
        unsigned sB = sA + TILE_B;
#pragma unroll
        for (int s = 0; s < 4; s++) {          // 4 x k16 per stage
            unsigned ci = (unsigned)(s*2) + hi;
            unsigned a[2][4], b[4][4];
#pragma unroll
            for (int mt = 0; mt < 2; mt++)
                LDSM_X4(a[mt], sA + aoff[mt] + ((ci ^ amask[mt]) << 4));
#pragma unroll
            for (int p = 0; p < 4; p++)
                LDSM_X4(b[p], sB + boff[p] + ((ci ^ bmask[p]) << 4));
#pragma unroll
            for (int mt = 0; mt < 2; mt++)
#pragma unroll
                for (int p = 0; p < 4; p++) {
                    MMA_F16(c[mt][2*p],   a[mt], b[p][0], b[p][2]);
                    MMA_F16(c[mt][2*p+1], a[mt], b[p][1], b[p][3]);
                }
        }
    }

    // epilogue
    float* Cf = (float*)Cv;
    __half* Ch = (__half*)Cv;
#pragma unroll
    for (int mt = 0; mt < 2; mt++) {
        int row0 = m0 + wy*32 + mt*16 + g;
#pragma unroll
        for (int nt = 0; nt < 8; nt++) {
            int col = n0 + wx*64 + nt*8 + tg*2;
            if (col >= N) continue;
#pragma unroll
            for (int hf = 0; hf < 2; hf++) {
                int r = row0 + hf*8;
                float v0 = c[mt][nt][hf*2+0] + bias[col];
                float v1 = c[mt][nt][hf*2+1] + bias[col+1];
                if (mode == 1) {
                    v0 += residual[(size_t)r*ldC + col];
                    v1 += residual[(size_t)r*ldC + col + 1];
                    *(float2*)&Cf[(size_t)r*ldC + col] = make_float2(v0, v1);
                } else if (mode == 2) {
                    *(__half2*)&Ch[(size_t)r*ldC + col] =
                        __floats2half2_rn(gelu_fast(v0), gelu_fast(v1));
                } else {
                    *(float2*)&Cf[(size_t)r*ldC + col] = make_float2(v0, v1);
                }
            }
        }
    }
}

// ---------------- attention: fp16 MMA, AQ=128, fused RoPE, register softmax --
#define AQ2 128
#define AK2 64
#define QKS_H 88     // Qs/Ks row stride in halfs (80 used, k-pad 72..79 zero)
#define PVS_H 72     // Ps/Vs row stride in halfs (64 used)

__device__ __forceinline__ int seg_of(int t, const int* offs) {
    int s = 0;
#pragma unroll
    for (int i = 1; i <= 6; i++) if (offs[i] <= t) s = i;
    return s;
}

// smem halfs: Q 128*88, K 64*88, V 72*72, P 128*72
#define ATTN_SMEM ((AQ2*QKS_H + AK2*QKS_H + HD*PVS_H + AQ2*PVS_H)*2 + (64+8)*4)

__global__ void __launch_bounds__(256)
attn2_kernel(const float* __restrict__ qkv, const float* __restrict__ fc,
             const int* __restrict__ offs, __half* __restrict__ out) {
    extern __shared__ char sm[];
    __half* Qh = (__half*)sm;
    __half* Kh = Qh + AQ2*QKS_H;
    __half* Vh = Kh + AK2*QKS_H;
    __half* Ph = Vh + HD*PVS_H;
    int* segk  = (int*)(Ph + AQ2*PVS_H);
    int* soffs = segk + 64;

    unsigned sbase = smem_u32(sm);
    unsigned uQ = sbase;
    unsigned uK = uQ + AQ2*QKS_H*2;
    unsigned uV = uK + AK2*QKS_H*2;
    unsigned uP = uV + HD*PVS_H*2;

    int tid = threadIdx.x, warp = tid >> 5, lane = tid & 31;
    int g = lane >> 2, tg = lane & 3;
    int h = blockIdx.y, q0 = blockIdx.x*AQ2;

    if (tid < 7) soffs[tid] = offs[tid];

    // zero k-pad halfs 72..79 of Qs (all 128 rows) and Ks (64 rows) once
    for (int t = tid; t < AQ2 + AK2; t += 256) {
        if (t < AQ2) *(uint4*)&Qh[t*QKS_H + 72] = make_uint4(0,0,0,0);
        else         *(uint4*)&Kh[(t-AQ2)*QKS_H + 72] = make_uint4(0,0,0,0);
    }

    // stage Q with fused RoPE -> fp16
    for (int t = tid; t < AQ2*18; t += 256) {
        int row = t/18, ch = t - row*18;
        int tok = q0 + row, d0 = ch*4;
        float4 v = *(const float4*)&qkv[(size_t)tok*QKV_N + h*HD + d0];
        float2 cs0 = *(const float2*)&fc[(size_t)tok*HD + d0];
        float2 cs1 = *(const float2*)&fc[(size_t)tok*HD + d0 + 2];
        __half2 h0 = __floats2half2_rn(v.x*cs0.x - v.y*cs0.y, v.x*cs0.y + v.y*cs0.x);
        __half2 h1 = __floats2half2_rn(v.z*cs1.x - v.w*cs1.y, v.z*cs1.y + v.w*cs1.x);
        *(__half2*)&Qh[row*QKS_H + d0]     = h0;
        *(__half2*)&Qh[row*QKS_H + d0 + 2] = h1;
    }
    __syncthreads();

    int r1 = warp*16 + g, r2 = r1 + 8;
    int sq1 = seg_of(q0 + r1, soffs);
    int sq2 = seg_of(q0 + r2, soffs);

    float m1 = -1e30f, m2 = -1e30f, l1 = 0.f, l2 = 0.f;
    float co[9][4];
#pragma unroll
    for (int nt = 0; nt < 9; nt++)
#pragma unroll
        for (int i = 0; i < 4; i++) co[nt][i] = 0.f;

    unsigned hi = (unsigned)(lane >> 4);
    unsigned offQ = (unsigned)((warp*16 + (lane & 15))*QKS_H*2) + hi*16;
    unsigned offP = (unsigned)((warp*16 + (lane & 15))*PVS_H*2) + hi*16;
    unsigned offK[4], offV[4];
#pragma unroll
    for (int p = 0; p < 4; p++) {
        offK[p] = (unsigned)((p*16 + (lane & 15))*QKS_H*2) + hi*16;
        offV[p] = (unsigned)((p*16 + (lane & 15))*PVS_H*2) + hi*16;
    }
    unsigned offV8 = (unsigned)((64 + (lane & 7))*PVS_H*2) + ((unsigned)((lane >> 3) & 1))*16;

    const float scale = 0.11785113019775793f;   // 1/sqrt(72)

    for (int j0 = 0; j0 < S_TOK; j0 += AK2) {
        __syncthreads();
        // stage K (rope->fp16) and V transposed [d][tok] fp16
        for (int t = tid; t < AK2*18; t += 256) {
            int row = t/18, ch = t - row*18;
            int tok = j0 + row, d0 = ch*4;
            float4 v = *(const float4*)&qkv[(size_t)tok*QKV_N + HID + h*HD + d0];
            float2 cs0 = *(const float2*)&fc[(size_t)tok*HD + d0];
            float2 cs1 = *(const float2*)&fc[(size_t)tok*HD + d0 + 2];
            __half2 h0 = __floats2half2_rn(v.x*cs0.x - v.y*cs0.y, v.x*cs0.y + v.y*cs0.x);
            __half2 h1 = __floats2half2_rn(v.z*cs1.x - v.w*cs1.y, v.z*cs1.y + v.w*cs1.x);
            *(__half2*)&Kh[row*QKS_H + d0]     = h0;
            *(__half2*)&Kh[row*QKS_H + d0 + 2] = h1;
        }
        for (int t = tid; t < AK2*18; t += 256) {
            int row = t/18, ch = t - row*18;
            float4 v = *(const float4*)&qkv[(size_t)(j0+row)*QKV_N + 2*HID + h*HD + ch*4];
            int d0 = ch*4;
            Vh[(d0+0)*PVS_H + row] = __float2half_rn(v.x);
            Vh[(d0+1)*PVS_H + row] = __float2half_rn(v.y);
            Vh[(d0+2)*PVS_H + row] = __float2half_rn(v.z);
            Vh[(d0+3)*PVS_H + row] = __float2half_rn(v.w);
        }
        if (tid < 64) segk[tid] = seg_of(j0 + tid, soffs);
        __syncthreads();

        // ---- S = Q K^T : 5 k16 steps over padded k=80 ----
        float sc[8][4];
#pragma unroll
        for (int nt = 0; nt < 8; nt++)
#pragma unroll
            for (int i = 0; i < 4; i++) sc[nt][i] = 0.f;
#pragma unroll
        for (int s = 0; s < 5; s++) {
            unsigned a[4], b[4][4];
            LDSM_X4(a, uQ + offQ + s*32);
#pragma unroll
            for (int p = 0; p < 4; p++) LDSM_X4(b[p], uK + offK[p] + s*32);
#pragma unroll
            for (int p = 0; p < 4; p++) {
                MMA_F16(sc[2*p],   a, b[p][0], b[p][2]);
                MMA_F16(sc[2*p+1], a, b[p][1], b[p][3]);
            }
        }
        // ---- bias + register softmax ----
        float mx1 = -1e30f, mx2 = -1e30f;
#pragma unroll
        for (int nt = 0; nt < 8; nt++) {
            int col = nt*8 + tg*2;
            int k0s = segk[col], k1s = segk[col+1];
            sc[nt][0] = sc[nt][0]*scale + (sq1 == k0s ? 1.f : 0.f);
            sc[nt][1] = sc[nt][1]*scale + (sq1 == k1s ? 1.f : 0.f);
            sc[nt][2] = sc[nt][2]*scale + (sq2 == k0s ? 1.f : 0.f);
            sc[nt][3] = sc[nt][3]*scale + (sq2 == k1s ? 1.f : 0.f);
            mx1 = fmaxf(mx1, fmaxf(sc[nt][0], sc[nt][1]));
            mx2 = fmaxf(mx2, fmaxf(sc[nt][2], sc[nt][3]));
        }
        mx1 = fmaxf(mx1, __shfl_xor_sync(0xffffffffu, mx1, 1, 4));
        mx1 = fmaxf(mx1, __shfl_xor_sync(0xffffffffu, mx1, 2, 4));
        mx2 = fmaxf(mx2, __shfl_xor_sync(0xffffffffu, mx2, 1, 4));
        mx2 = fmaxf(mx2, __shfl_xor_sync(0xffffffffu, mx2, 2, 4));
        float mn1 = fmaxf(m1, mx1), mn2 = fmaxf(m2, mx2);
        float f1 = __expf(m1 - mn1), f2 = __expf(m2 - mn2);
        m1 = mn1; m2 = mn2;
        float s1 = 0.f, s2 = 0.f;
#pragma unroll
        for (int nt = 0; nt < 8; nt++) {
            float p0 = __expf(sc[nt][0] - m1);
            float p1 = __expf(sc[nt][1] - m1);
            float p2 = __expf(sc[nt][2] - m2);
            float p3 = __expf(sc[nt][3] - m2);
            s1 += p0 + p1; s2 += p2 + p3;
            int col = nt*8 + tg*2;
            *(__half2*)&Ph[r1*PVS_H + col] = __floats2half2_rn(p0, p1);
            *(__half2*)&Ph[r2*PVS_H + col] = __floats2half2_rn(p2, p3);
        }
        s1 += __shfl_xor_sync(0xffffffffu, s1, 1, 4);
        s1 += __shfl_xor_sync(0xffffffffu, s1, 2, 4);
        s2 += __shfl_xor_sync(0xffffffffu, s2, 1, 4);
        s2 += __shfl_xor_sync(0xffffffffu, s2, 2, 4);
        l1 = l1*f1 + s1; l2 = l2*f2 + s2;
#pragma unroll
        for (int nt = 0; nt < 9; nt++) {
            co[nt][0] *= f1; co[nt][1] *= f1;
            co[nt][2] *= f2; co[nt][3] *= f2;
        }
        __syncthreads();
        // ---- O += P V : 4 k16 steps over 64 toks ----
#pragma unroll
        for (int s = 0; s < 4; s++) {
            unsigned a[4], b[4][4], b8[2];
            LDSM_X4(a, uP + offP + s*32);
#pragma unroll
            for (int p = 0; p < 4; p++) LDSM_X4(b[p], uV + offV[p] + s*32);
            LDSM_X2(b8, uV + offV8 + s*32);
#pragma unroll
            for (int p = 0; p < 4; p++) {
                MMA_F16(co[2*p],   a, b[p][0], b[p][2]);
                MMA_F16(co[2*p+1], a, b[p][1], b[p][3]);
            }
            MMA_F16(co[8], a, b8[0], b8[1]);
        }
    }

    // epilogue: fp16 out (feeds Wo GEMM A operand); d0 = nt*8+tg*2 < 72 always
    float i1 = 1.f/l1, i2 = 1.f/l2;
#pragma unroll
    for (int nt = 0; nt < 9; nt++) {
        int d0 = nt*8 + tg*2;
        *(__half2*)&out[(size_t)(q0+r1)*HID + h*HD + d0] =
            __floats2half2_rn(co[nt][0]*i1, co[nt][1]*i1);
        *(__half2*)&out[(size_t)(q0+r2)*HID + h*HD + d0] =
            __floats2half2_rn(co[nt][2]*i2, co[nt][3]*i2);
    }
}

// ---------------- launch ----------------
extern "C" void kernel_launch(void* const* d_in, const int* in_sizes, int n_in,
                              void* d_out, int out_size) {
    const float* x      = (const float*)d_in[0];
    const int*   offs   = (const int*)  d_in[1];
    const float* fc     = (const float*)d_in[2];
    const float* ln0_g  = (const float*)d_in[3];
    const float* ln0_b  = (const float*)d_in[4];
    const float* wqkv_w = (const float*)d_in[5];
    const float* wqkv_b = (const float*)d_in[6];
    const float* wo_w   = (const float*)d_in[7];
    const float* wo_b   = (const float*)d_in[8];
    const float* ln1_g  = (const float*)d_in[9];
    const float* ln1_b  = (const float*)d_in[10];
    const float* w1     = (const float*)d_in[11];
    const float* b1     = (const float*)d_in[12];
    const float* w2     = (const float*)d_in[13];
    const float* b2     = (const float*)d_in[14];
    float* out = (float*)d_out;

    float *qkv, *x2;
    __half *h0h, *attnh, *h1h, *mlph, *wqkvth, *woth, *w1th, *w2th;
    cudaGetSymbolAddress((void**)&qkv,    g_qkv);
    cudaGetSymbolAddress((void**)&x2,     g_x2);
    cudaGetSymbolAddress((void**)&h0h,    g_h0h);
    cudaGetSymbolAddress((void**)&attnh,  g_attnh);
    cudaGetSymbolAddress((void**)&h1h,    g_h1h);
    cudaGetSymbolAddress((void**)&mlph,   g_mlph);
    cudaGetSymbolAddress((void**)&wqkvth, g_wqkvth);
    cudaGetSymbolAddress((void**)&woth,   g_woth);
    cudaGetSymbolAddress((void**)&w1th,   g_w1th);
    cudaGetSymbolAddress((void**)&w2th,   g_w2th);

    cudaFuncSetAttribute(hgemm, cudaFuncAttributeMaxDynamicSharedMemorySize, GEMM_SMEM);
    cudaFuncSetAttribute(attn2_kernel, cudaFuncAttributeMaxDynamicSharedMemorySize, ATTN_SMEM);

    // 0. transpose weights -> [N][K] fp16
    transpose_kernel<<<dim3((QKV_N+31)/32, (HID+31)/32), dim3(32,8)>>>(wqkv_w, wqkvth, HID, QKV_N, HID);
    transpose_kernel<<<dim3((HID+31)/32, (HID+31)/32),   dim3(32,8)>>>(wo_w,   woth,   HID, HID,   HID);
    transpose_kernel<<<dim3((MLP_DIM+31)/32, (HID+31)/32), dim3(32,8)>>>(w1, w1th, HID, MLP_DIM, HID);
    transpose_kernel<<<dim3((HID+31)/32, (MLP_DIM+31)/32), dim3(32,8)>>>(w2, w2th, MLP_DIM, HID, MLP_P2);

    // 1. LN0 -> fp16
    ln_kernel<<<S_TOK, 256>>>(x, ln0_g, ln0_b, h0h);
    // 2. QKV = h0 @ wqkv + b  (fp32 out; rope at attention staging)
    hgemm<<<dim3(QKV_N/128, S_TOK/128), 256, GEMM_SMEM>>>(
        h0h, HID, wqkvth, HID, wqkv_b, nullptr, qkv, QKV_N, QKV_N, HID/GBK, 0);
    // 3. attention (fused rope) -> fp16
    attn2_kernel<<<dim3(S_TOK/AQ2, NH), 256, ATTN_SMEM>>>(qkv, fc, offs, attnh);
    // 4. x2 = x + attn @ wo + b  (fp32 out)
    hgemm<<<dim3(HID/128, S_TOK/128), 256, GEMM_SMEM>>>(
        attnh, HID, woth, HID, wo_b, x, x2, HID, HID, HID/GBK, 1);
    // 5. LN1 -> fp16
    ln_kernel<<<S_TOK, 256>>>(x2, ln1_g, ln1_b, h1h);
    // 6. mlp = gelu(h1 @ w1 + b1) -> fp16 (padded ldC)
    hgemm<<<dim3((MLP_DIM+127)/128, S_TOK/128), 256, GEMM_SMEM>>>(
        h1h, HID, w1th, HID, b1, nullptr, mlph, MLP_P2, MLP_DIM, HID/GBK, 2);
    // 7. out = x2 + mlp @ w2 + b2  (K padded to 4352 with zeros)
    hgemm<<<dim3(HID/128, S_TOK/128), 256, GEMM_SMEM>>>(
        mlph, MLP_P2, w2th, MLP_P2, b2, x2, out, HID, HID, MLP_P2/GBK, 1);
}